// round 1
// baseline (speedup 1.0000x reference)
#include <cuda_runtime.h>
#include <math.h>

#define TOKENS 4096
#define DMODEL 1024
#define SEQ    1024
#define NHEAD  16
#define HDIM   64
#define DFF_   4096

// ---------------- scratch (device globals: allocation-free) ----------------
__device__ float g_h[TOKENS * DMODEL];            // 16 MB
__device__ float g_qkv[TOKENS * 3 * DMODEL];      // 48 MB (also holds ckv)
__device__ float g_attn[TOKENS * DMODEL];         // 16 MB
__device__ float g_proj[TOKENS * DMODEL];         // 16 MB
__device__ float g_ffbuf[16777216];               // 64 MB (4096 x 4096)

// ---------------- step-embed add ----------------
__global__ void add_step_kernel(const float* __restrict__ hidden,
                                const float* __restrict__ se,
                                const int* __restrict__ ts,
                                float* __restrict__ out)
{
    int idx = blockIdx.x * blockDim.x + threadIdx.x;
    int c = ts[0];
    if (c > 19) c = 19;
    out[idx] = hidden[idx] + se[c * DMODEL + (idx & (DMODEL - 1))];
}

// ---------------- SGEMM: C = A @ W + bias, optional exact GELU ----------------
// A: [M,K] row-major, W: [K,N] row-major. M,N % 128 == 0, K % 16 == 0.
template <int ACT>
__global__ __launch_bounds__(256) void sgemm_kernel(
    const float* __restrict__ A, const float* __restrict__ W,
    const float* __restrict__ bias, float* __restrict__ C,
    int M, int N, int K)
{
    __shared__ float As[16][128];
    __shared__ float Bs[16][128];
    int tid = threadIdx.x;
    int bm = blockIdx.y * 128, bn = blockIdx.x * 128;
    int tm = (tid >> 4) * 8, tn = (tid & 15) * 8;

    float cr[8][8];
#pragma unroll
    for (int i = 0; i < 8; i++)
#pragma unroll
        for (int j = 0; j < 8; j++) cr[i][j] = 0.f;

    for (int k0 = 0; k0 < K; k0 += 16) {
#pragma unroll
        for (int i = 0; i < 2; i++) {
            int idx = tid + i * 256;
            int row = idx >> 2, c4 = idx & 3;
            float4 t = *(const float4*)(A + (size_t)(bm + row) * K + k0 + c4 * 4);
            As[c4 * 4 + 0][row] = t.x;
            As[c4 * 4 + 1][row] = t.y;
            As[c4 * 4 + 2][row] = t.z;
            As[c4 * 4 + 3][row] = t.w;
        }
#pragma unroll
        for (int i = 0; i < 2; i++) {
            int idx = tid + i * 256;
            int row = idx >> 5, c4 = idx & 31;
            *(float4*)&Bs[row][c4 * 4] =
                *(const float4*)(W + (size_t)(k0 + row) * N + bn + c4 * 4);
        }
        __syncthreads();
#pragma unroll
        for (int k = 0; k < 16; k++) {
            float ar[8], br[8];
            *(float4*)&ar[0] = *(float4*)&As[k][tm];
            *(float4*)&ar[4] = *(float4*)&As[k][tm + 4];
            *(float4*)&br[0] = *(float4*)&Bs[k][tn];
            *(float4*)&br[4] = *(float4*)&Bs[k][tn + 4];
#pragma unroll
            for (int i = 0; i < 8; i++)
#pragma unroll
                for (int j = 0; j < 8; j++)
                    cr[i][j] = fmaf(ar[i], br[j], cr[i][j]);
        }
        __syncthreads();
    }

    float bb[8];
#pragma unroll
    for (int j = 0; j < 8; j++) bb[j] = bias[bn + tn + j];
#pragma unroll
    for (int i = 0; i < 8; i++) {
        float* crow = C + (size_t)(bm + tm + i) * N + bn + tn;
        float vals[8];
#pragma unroll
        for (int j = 0; j < 8; j++) {
            float x = cr[i][j] + bb[j];
            if (ACT == 1) x = 0.5f * x * (1.f + erff(x * 0.70710678118654752f));
            vals[j] = x;
        }
        *(float4*)&crow[0] = *(float4*)&vals[0];
        *(float4*)&crow[4] = *(float4*)&vals[4];
    }
}

// ---------------- flash attention (online softmax), 32 queries/block ----------------
// Q element: Q[(b*S+s)*qstride + head*64 + d]
// K element: KV[(b*S+s)*kvstride + koff + head*64 + d]
// V element: KV[(b*S+s)*kvstride + voff + head*64 + d]
// out: [B,S,H*HD] row-major.
__global__ __launch_bounds__(128) void attn_kernel(
    const float* __restrict__ Q, int qstride,
    const float* __restrict__ KV, int kvstride, int koff, int voff,
    const float* __restrict__ rpb, float* __restrict__ out, int useBias)
{
    __shared__ float ks[64][68];
    __shared__ float vs[64][68];
    __shared__ float ps[32][68];

    int tid = threadIdx.x;
    int r = tid >> 2, sub = tid & 3;
    int qt = blockIdx.x, head = blockIdx.y, b = blockIdx.z;
    int qglob = qt * 32 + r;

    const float* qrow = Q + (size_t)(b * SEQ + qglob) * qstride + head * HDIM;
    float qreg[64];
#pragma unroll
    for (int i = 0; i < 16; i++) {
        float4 t = *(const float4*)(qrow + i * 4);
        qreg[4 * i] = t.x; qreg[4 * i + 1] = t.y;
        qreg[4 * i + 2] = t.z; qreg[4 * i + 3] = t.w;
    }

    float acc[16];
#pragma unroll
    for (int i = 0; i < 16; i++) acc[i] = 0.f;
    float m_i = -1e30f, l_i = 0.f;
    const float scale = 0.125f;  // 64^-0.5

    for (int kt = 0; kt < 16; kt++) {
        int base = b * SEQ + kt * 64;
#pragma unroll
        for (int i = 0; i < 8; i++) {
            int idx = tid + i * 128;
            int row = idx >> 4, c4 = idx & 15;
            *(float4*)&ks[row][c4 * 4] = *(const float4*)(
                KV + (size_t)(base + row) * kvstride + koff + head * HDIM + c4 * 4);
            *(float4*)&vs[row][c4 * 4] = *(const float4*)(
                KV + (size_t)(base + row) * kvstride + voff + head * HDIM + c4 * 4);
        }
        __syncthreads();

        float sc[16];
#pragma unroll
        for (int kk = 0; kk < 16; kk++) {
            int j = kk * 4 + sub;
            float s = 0.f;
#pragma unroll
            for (int d = 0; d < 64; d++) s = fmaf(qreg[d], ks[j][d], s);
            s *= scale;
            if (useBias) s += __ldg(&rpb[qglob - (kt * 64 + j) + 1023]);
            sc[kk] = s;
        }

        float tmax = sc[0];
#pragma unroll
        for (int kk = 1; kk < 16; kk++) tmax = fmaxf(tmax, sc[kk]);
        tmax = fmaxf(tmax, __shfl_xor_sync(0xffffffffu, tmax, 1));
        tmax = fmaxf(tmax, __shfl_xor_sync(0xffffffffu, tmax, 2));

        float newm = fmaxf(m_i, tmax);
        float corr = expf(m_i - newm);
        l_i *= corr;
#pragma unroll
        for (int i = 0; i < 16; i++) acc[i] *= corr;
        m_i = newm;

        float psum = 0.f;
#pragma unroll
        for (int kk = 0; kk < 16; kk++) {
            float p = expf(sc[kk] - m_i);
            psum += p;
            ps[r][kk * 4 + sub] = p;
        }
        l_i += psum;
        __syncthreads();

#pragma unroll
        for (int j = 0; j < 64; j++) {
            float pj = ps[r][j];
#pragma unroll
            for (int d = 0; d < 16; d++)
                acc[d] = fmaf(pj, vs[j][sub * 16 + d], acc[d]);
        }
        __syncthreads();
    }

    l_i += __shfl_xor_sync(0xffffffffu, l_i, 1);
    l_i += __shfl_xor_sync(0xffffffffu, l_i, 2);
    float inv = 1.f / l_i;

    float* orow = out + (size_t)(b * SEQ + qglob) * DMODEL + head * HDIM + sub * 16;
#pragma unroll
    for (int i = 0; i < 4; i++) {
        float4 t = make_float4(acc[4 * i] * inv, acc[4 * i + 1] * inv,
                               acc[4 * i + 2] * inv, acc[4 * i + 3] * inv);
        *(float4*)(orow + 4 * i) = t;
    }
}

// ---------------- residual + LayerNorm (row = 1024) ----------------
__global__ __launch_bounds__(256) void ln_kernel(
    const float* __restrict__ A, const float* __restrict__ Bx,
    const float* __restrict__ g, const float* __restrict__ beta,
    float* __restrict__ out)
{
    int row = blockIdx.x, tid = threadIdx.x;
    const float4 va = ((const float4*)(A + (size_t)row * DMODEL))[tid];
    const float4 vb = ((const float4*)(Bx + (size_t)row * DMODEL))[tid];
    float x0 = va.x + vb.x, x1 = va.y + vb.y, x2 = va.z + vb.z, x3 = va.w + vb.w;

    float s = x0 + x1 + x2 + x3;
    float ss = x0 * x0 + x1 * x1 + x2 * x2 + x3 * x3;
#pragma unroll
    for (int o = 16; o > 0; o >>= 1) {
        s  += __shfl_xor_sync(0xffffffffu, s, o);
        ss += __shfl_xor_sync(0xffffffffu, ss, o);
    }
    __shared__ float sb[16];
    int warp = tid >> 5, lane = tid & 31;
    if (lane == 0) { sb[warp] = s; sb[8 + warp] = ss; }
    __syncthreads();
    if (warp == 0) {
        float s2  = (lane < 8) ? sb[lane] : 0.f;
        float ss2 = (lane < 8) ? sb[8 + lane] : 0.f;
#pragma unroll
        for (int o = 4; o > 0; o >>= 1) {
            s2  += __shfl_xor_sync(0xffffffffu, s2, o);
            ss2 += __shfl_xor_sync(0xffffffffu, ss2, o);
        }
        if (lane == 0) { sb[0] = s2; sb[8] = ss2; }
    }
    __syncthreads();
    float mu  = sb[0] * (1.f / 1024.f);
    float var = sb[8] * (1.f / 1024.f) - mu * mu;
    float rstd = rsqrtf(var + 1e-5f);

    float4 go = ((const float4*)g)[tid];
    float4 bo = ((const float4*)beta)[tid];
    float4 r4;
    r4.x = (x0 - mu) * rstd * go.x + bo.x;
    r4.y = (x1 - mu) * rstd * go.y + bo.y;
    r4.z = (x2 - mu) * rstd * go.z + bo.z;
    r4.w = (x3 - mu) * rstd * go.w + bo.w;
    ((float4*)(out + (size_t)row * DMODEL))[tid] = r4;
}

// ---------------- orchestration ----------------
extern "C" void kernel_launch(void* const* d_in, const int* in_sizes, int n_in,
                              void* d_out, int out_size)
{
    const float* hidden = (const float*)d_in[0];
    const float* source = (const float*)d_in[1];
    const int*   tstep  = (const int*)d_in[2];
    const float* sembed = (const float*)d_in[3];
    const float* rpb    = (const float*)d_in[4];
    const float* Wqkv = (const float*)d_in[5],  *bqkv = (const float*)d_in[6];
    const float* Wo   = (const float*)d_in[7],  *bo   = (const float*)d_in[8];
    const float* Wcq  = (const float*)d_in[9],  *bcq  = (const float*)d_in[10];
    const float* Wckv = (const float*)d_in[11], *bckv = (const float*)d_in[12];
    const float* Wco  = (const float*)d_in[13], *bco  = (const float*)d_in[14];
    const float* W1   = (const float*)d_in[15], *b1   = (const float*)d_in[16];
    const float* W2   = (const float*)d_in[17], *b2   = (const float*)d_in[18];
    const float* gs = (const float*)d_in[19], *bts = (const float*)d_in[20];
    const float* gc = (const float*)d_in[21], *btc = (const float*)d_in[22];
    const float* gf = (const float*)d_in[23], *btf = (const float*)d_in[24];
    float* out = (float*)d_out;

    float *ph, *pqkv, *pattn, *pproj, *pff;
    cudaGetSymbolAddress((void**)&ph,    g_h);
    cudaGetSymbolAddress((void**)&pqkv,  g_qkv);
    cudaGetSymbolAddress((void**)&pattn, g_attn);
    cudaGetSymbolAddress((void**)&pproj, g_proj);
    cudaGetSymbolAddress((void**)&pff,   g_ffbuf);

    // h0 = hidden + step_embed[clamp(think_step)]
    add_step_kernel<<<TOKENS * DMODEL / 256, 256>>>(hidden, sembed, tstep, ph);

    // qkv = h0 @ Wqkv + bqkv
    dim3 gqkv(3 * DMODEL / 128, TOKENS / 128);
    sgemm_kernel<0><<<gqkv, 256>>>(ph, Wqkv, bqkv, pqkv, TOKENS, 3 * DMODEL, DMODEL);

    // self-attention with rel-pos bias
    dim3 ga(SEQ / 32, NHEAD, 4);
    attn_kernel<<<ga, 128>>>(pqkv, 3 * DMODEL, pqkv, 3 * DMODEL, DMODEL, 2 * DMODEL,
                             rpb, pattn, 1);

    // so = attn @ Wo + bo ; h = LN(h0 + so)
    dim3 g1k(DMODEL / 128, TOKENS / 128);
    sgemm_kernel<0><<<g1k, 256>>>(pattn, Wo, bo, pproj, TOKENS, DMODEL, DMODEL);
    ln_kernel<<<TOKENS, 256>>>(ph, pproj, gs, bts, ph);

    // cross-attention: cq = h @ Wcq, ckv = source @ Wckv
    sgemm_kernel<0><<<g1k, 256>>>(ph, Wcq, bcq, pattn, TOKENS, DMODEL, DMODEL);
    dim3 gckv(2 * DMODEL / 128, TOKENS / 128);
    sgemm_kernel<0><<<gckv, 256>>>(source, Wckv, bckv, pqkv, TOKENS, 2 * DMODEL, DMODEL);
    attn_kernel<<<ga, 128>>>(pattn, DMODEL, pqkv, 2 * DMODEL, 0, DMODEL,
                             rpb, pproj, 0);

    // co = cattn @ Wco + bco ; h = LN(h + co)
    sgemm_kernel<0><<<g1k, 256>>>(pproj, Wco, bco, pattn, TOKENS, DMODEL, DMODEL);
    ln_kernel<<<TOKENS, 256>>>(ph, pattn, gc, btc, ph);

    // FFN: gelu(h @ W1 + b1) @ W2 + b2 ; out = LN(h + ff)
    dim3 gff1(DFF_ / 128, TOKENS / 128);
    sgemm_kernel<1><<<gff1, 256>>>(ph, W1, b1, pff, TOKENS, DFF_, DMODEL);
    sgemm_kernel<0><<<g1k, 256>>>(pff, W2, b2, pproj, TOKENS, DMODEL, DFF_);
    ln_kernel<<<TOKENS, 256>>>(ph, pproj, gf, btf, out);
}

// round 3
// speedup vs baseline: 1.5229x; 1.5229x over previous
#include <cuda_runtime.h>
#include <cuda_bf16.h>
#include <cstdint>
#include <math.h>

#define TOKENS 4096
#define DMODEL 1024
#define SEQ    1024
#define NHEAD  16
#define HDIM   64
#define DFF_   4096

// ---------------- scratch (device globals: allocation-free) ----------------
__device__ float g_h[TOKENS * DMODEL];                  // residual stream f32
__device__ float g_qkv[TOKENS * 3 * DMODEL];            // qkv / ckv f32
__device__ float g_attn[TOKENS * DMODEL];
__device__ float g_proj[TOKENS * DMODEL];
__device__ __nv_bfloat16 g_ahi[TOKENS * DMODEL];        // current GEMM A (hi)
__device__ __nv_bfloat16 g_alo[TOKENS * DMODEL];        // current GEMM A (lo)
__device__ __nv_bfloat16 g_ffhi[TOKENS * DFF_];         // ff activation hi
__device__ __nv_bfloat16 g_fflo[TOKENS * DFF_];
__device__ __nv_bfloat16 g_whi[16777216];               // all weights, transposed [N][K]
__device__ __nv_bfloat16 g_wlo[16777216];

// weight offsets (elements) in g_whi/g_wlo
#define OFF_QKV 0
#define OFF_O   3145728
#define OFF_CQ  4194304
#define OFF_CKV 5242880
#define OFF_CO  7340032
#define OFF_W1  8388608
#define OFF_W2  12582912

// ---------------- helpers ----------------
__device__ __forceinline__ uint32_t smem_u32(const void* p) {
    uint32_t a;
    asm("{ .reg .u64 t; cvta.to.shared.u64 t, %1; cvt.u32.u64 %0, t; }" : "=r"(a) : "l"(p));
    return a;
}
__device__ __forceinline__ void cpa16(uint32_t d, const void* g) {
    asm volatile("cp.async.cg.shared.global [%0], [%1], 16;" :: "r"(d), "l"(g));
}
#define CP_COMMIT() asm volatile("cp.async.commit_group;" ::: "memory")
#define LDSM4(r, a) \
    asm volatile("ldmatrix.sync.aligned.m8n8.x4.shared.b16 {%0,%1,%2,%3}, [%4];" \
        : "=r"((r)[0]), "=r"((r)[1]), "=r"((r)[2]), "=r"((r)[3]) : "r"(a))

__device__ __forceinline__ void mma_bf16(float* d, const uint32_t* a, const uint32_t* b) {
    asm volatile("mma.sync.aligned.m16n8k16.row.col.f32.bf16.bf16.f32 "
                 "{%0,%1,%2,%3}, {%4,%5,%6,%7}, {%8,%9}, {%0,%1,%2,%3};"
                 : "+f"(d[0]), "+f"(d[1]), "+f"(d[2]), "+f"(d[3])
                 : "r"(a[0]), "r"(a[1]), "r"(a[2]), "r"(a[3]), "r"(b[0]), "r"(b[1]));
}
__device__ __forceinline__ void split1(float x, __nv_bfloat16& h, __nv_bfloat16& l) {
    h = __float2bfloat16_rn(x);
    l = __float2bfloat16_rn(x - __bfloat162float(h));
}

// ---------------- bf16x3 HMMA GEMM ----------------
// A: hi/lo bf16 [M][K]; W: hi/lo bf16 [N][K] (transposed). C = A@W^T + bias.
// Tile 128x128, K-chunk 64, double-buffered cp.async. 256 threads, 8 warps (2x4).
#define STG_A_LO 16384
#define STG_B_HI 32768
#define STG_B_LO 49152
#define STG_SZ   65536
#define SMEM_GM  131072

template <int ACT, int SPLITOUT>
__global__ __launch_bounds__(256) void gemm_mma(
    const __nv_bfloat16* __restrict__ Ahi, const __nv_bfloat16* __restrict__ Alo,
    const __nv_bfloat16* __restrict__ Bhi, const __nv_bfloat16* __restrict__ Blo,
    const float* __restrict__ bias, float* __restrict__ C,
    __nv_bfloat16* __restrict__ Chi, __nv_bfloat16* __restrict__ Clo,
    int M, int N, int K)
{
    extern __shared__ char smem[];
    uint32_t sb = smem_u32(smem);
    int tid = threadIdx.x, lane = tid & 31, wid = tid >> 5;
    int wm = wid & 1, wn = wid >> 1;                 // warp grid 2(m) x 4(n)
    int bm = blockIdx.y * 128, bn = blockIdx.x * 128;

    float acc[4][4][4];
#pragma unroll
    for (int a = 0; a < 4; a++)
#pragma unroll
        for (int b = 0; b < 4; b++)
#pragma unroll
            for (int c = 0; c < 4; c++) acc[a][b][c] = 0.f;

    auto load_stage = [&](int kc, int s) {
        uint32_t base = sb + s * STG_SZ;
        const __nv_bfloat16* srcs[4] = {Ahi, Alo, Bhi, Blo};
        int rbs[4] = {bm, bm, bn, bn};
#pragma unroll
        for (int m = 0; m < 4; m++) {
            const __nv_bfloat16* src = srcs[m];
            int rb = rbs[m];
#pragma unroll
            for (int i = 0; i < 4; i++) {
                int idx = tid + i * 256;
                int row = idx >> 3, ch = idx & 7;
                uint32_t dst = base + m * 16384 + row * 128 + ((ch ^ (row & 7)) << 4);
                cpa16(dst, src + (size_t)(rb + row) * K + kc * 64 + ch * 8);
            }
        }
        CP_COMMIT();
    };

    const int NC = K >> 6;
    load_stage(0, 0);

    for (int c = 0; c < NC; c++) {
        if (c + 1 < NC) {
            load_stage(c + 1, (c + 1) & 1);
            asm volatile("cp.async.wait_group 1;" ::: "memory");
        } else {
            asm volatile("cp.async.wait_group 0;" ::: "memory");
        }
        __syncthreads();

        uint32_t aBase = sb + (c & 1) * STG_SZ;
#pragma unroll
        for (int ks = 0; ks < 4; ks++) {
            uint32_t ah[4][4], al[4][4];
#pragma unroll
            for (int mt = 0; mt < 4; mt++) {
                int row = wm * 64 + mt * 16 + (lane & 15);
                int ch = ks * 2 + (lane >> 4);
                uint32_t ad = aBase + row * 128 + ((ch ^ (row & 7)) << 4);
                LDSM4(ah[mt], ad);
                LDSM4(al[mt], ad + STG_A_LO);
            }
            uint32_t bh[2][4], bl[2][4];
#pragma unroll
            for (int nh = 0; nh < 2; nh++) {
                int row = wn * 32 + nh * 16 + (lane & 7) + ((lane >> 4) << 3);
                int ch = ks * 2 + ((lane >> 3) & 1);
                uint32_t bd = aBase + STG_B_HI + row * 128 + ((ch ^ (row & 7)) << 4);
                LDSM4(bh[nh], bd);
                LDSM4(bl[nh], bd + 16384);
            }
#pragma unroll
            for (int mt = 0; mt < 4; mt++) {
#pragma unroll
                for (int nt = 0; nt < 4; nt++) {
                    uint32_t* B1 = &bh[nt >> 1][(nt & 1) * 2];
                    uint32_t* B2 = &bl[nt >> 1][(nt & 1) * 2];
                    mma_bf16(acc[mt][nt], ah[mt], B1);
                    mma_bf16(acc[mt][nt], ah[mt], B2);
                    mma_bf16(acc[mt][nt], al[mt], B1);
                }
            }
        }
        __syncthreads();
    }

    // epilogue
#pragma unroll
    for (int mt = 0; mt < 4; mt++) {
#pragma unroll
        for (int nt = 0; nt < 4; nt++) {
            int col = bn + wn * 32 + nt * 8 + (lane & 3) * 2;
            int r0 = bm + wm * 64 + mt * 16 + (lane >> 2);
            float bb0 = __ldg(&bias[col]), bb1 = __ldg(&bias[col + 1]);
#pragma unroll
            for (int half = 0; half < 2; half++) {
                int r = r0 + half * 8;
                float x0 = acc[mt][nt][half * 2 + 0] + bb0;
                float x1 = acc[mt][nt][half * 2 + 1] + bb1;
                if (ACT == 1) {
                    x0 = 0.5f * x0 * (1.f + erff(x0 * 0.70710678118654752f));
                    x1 = 0.5f * x1 * (1.f + erff(x1 * 0.70710678118654752f));
                }
                if (SPLITOUT) {
                    __nv_bfloat16 h0, l0, h1, l1;
                    split1(x0, h0, l0); split1(x1, h1, l1);
                    *(__nv_bfloat162*)&Chi[(size_t)r * N + col] = __nv_bfloat162(h0, h1);
                    *(__nv_bfloat162*)&Clo[(size_t)r * N + col] = __nv_bfloat162(l0, l1);
                } else {
                    *(float2*)&C[(size_t)r * N + col] = make_float2(x0, x1);
                }
            }
        }
    }
}

// ---------------- weight split+transpose: W[K][N] -> hi/lo [N][K] ----------------
__global__ __launch_bounds__(256) void wsplit_t(
    const float* __restrict__ W, __nv_bfloat16* __restrict__ hi,
    __nv_bfloat16* __restrict__ lo, int K, int N)
{
    __shared__ float s[32][33];
    int tx = threadIdx.x & 31, ty = threadIdx.x >> 5;
    int n0 = blockIdx.x * 32, k0 = blockIdx.y * 32;
#pragma unroll
    for (int i = 0; i < 4; i++)
        s[ty + 8 * i][tx] = W[(size_t)(k0 + ty + 8 * i) * N + n0 + tx];
    __syncthreads();
#pragma unroll
    for (int i = 0; i < 4; i++) {
        int n = ty + 8 * i;
        float v = s[tx][n];
        __nv_bfloat16 h, l;
        split1(v, h, l);
        hi[(size_t)(n0 + n) * K + k0 + tx] = h;
        lo[(size_t)(n0 + n) * K + k0 + tx] = l;
    }
}

// ---------------- activation split ----------------
__global__ void split_act(const float* __restrict__ in,
                          __nv_bfloat16* __restrict__ hi,
                          __nv_bfloat16* __restrict__ lo)
{
    int idx = blockIdx.x * 256 + threadIdx.x;
    float4 v = ((const float4*)in)[idx];
    __nv_bfloat16 h0, l0, h1, l1, h2, l2, h3, l3;
    split1(v.x, h0, l0); split1(v.y, h1, l1);
    split1(v.z, h2, l2); split1(v.w, h3, l3);
    ((__nv_bfloat162*)hi)[idx * 2]     = __nv_bfloat162(h0, h1);
    ((__nv_bfloat162*)hi)[idx * 2 + 1] = __nv_bfloat162(h2, h3);
    ((__nv_bfloat162*)lo)[idx * 2]     = __nv_bfloat162(l0, l1);
    ((__nv_bfloat162*)lo)[idx * 2 + 1] = __nv_bfloat162(l2, l3);
}

// ---------------- step-embed add (+split) ----------------
__global__ void add_step_kernel(const float* __restrict__ hidden,
                                const float* __restrict__ se,
                                const int* __restrict__ ts,
                                float* __restrict__ out,
                                __nv_bfloat16* __restrict__ hi,
                                __nv_bfloat16* __restrict__ lo)
{
    int idx = blockIdx.x * 256 + threadIdx.x;
    int c = ts[0];
    if (c > 19) c = 19;
    float4 h = ((const float4*)hidden)[idx];
    float4 s = ((const float4*)(se + c * DMODEL))[idx & 255];
    float4 o = make_float4(h.x + s.x, h.y + s.y, h.z + s.z, h.w + s.w);
    ((float4*)out)[idx] = o;
    __nv_bfloat16 h0, l0, h1, l1, h2, l2, h3, l3;
    split1(o.x, h0, l0); split1(o.y, h1, l1);
    split1(o.z, h2, l2); split1(o.w, h3, l3);
    ((__nv_bfloat162*)hi)[idx * 2]     = __nv_bfloat162(h0, h1);
    ((__nv_bfloat162*)hi)[idx * 2 + 1] = __nv_bfloat162(h2, h3);
    ((__nv_bfloat162*)lo)[idx * 2]     = __nv_bfloat162(l0, l1);
    ((__nv_bfloat162*)lo)[idx * 2 + 1] = __nv_bfloat162(l2, l3);
}

// ---------------- flash attention (unchanged from R1) ----------------
__global__ __launch_bounds__(128) void attn_kernel(
    const float* __restrict__ Q, int qstride,
    const float* __restrict__ KV, int kvstride, int koff, int voff,
    const float* __restrict__ rpb, float* __restrict__ out, int useBias)
{
    __shared__ float ks[64][68];
    __shared__ float vs[64][68];
    __shared__ float ps[32][68];

    int tid = threadIdx.x;
    int r = tid >> 2, sub = tid & 3;
    int qt = blockIdx.x, head = blockIdx.y, b = blockIdx.z;
    int qglob = qt * 32 + r;

    const float* qrow = Q + (size_t)(b * SEQ + qglob) * qstride + head * HDIM;
    float qreg[64];
#pragma unroll
    for (int i = 0; i < 16; i++) {
        float4 t = *(const float4*)(qrow + i * 4);
        qreg[4 * i] = t.x; qreg[4 * i + 1] = t.y;
        qreg[4 * i + 2] = t.z; qreg[4 * i + 3] = t.w;
    }

    float acc[16];
#pragma unroll
    for (int i = 0; i < 16; i++) acc[i] = 0.f;
    float m_i = -1e30f, l_i = 0.f;
    const float scale = 0.125f;

    for (int kt = 0; kt < 16; kt++) {
        int base = b * SEQ + kt * 64;
#pragma unroll
        for (int i = 0; i < 8; i++) {
            int idx = tid + i * 128;
            int row = idx >> 4, c4 = idx & 15;
            *(float4*)&ks[row][c4 * 4] = *(const float4*)(
                KV + (size_t)(base + row) * kvstride + koff + head * HDIM + c4 * 4);
            *(float4*)&vs[row][c4 * 4] = *(const float4*)(
                KV + (size_t)(base + row) * kvstride + voff + head * HDIM + c4 * 4);
        }
        __syncthreads();

        float sc[16];
#pragma unroll
        for (int kk = 0; kk < 16; kk++) {
            int j = kk * 4 + sub;
            float s = 0.f;
#pragma unroll
            for (int d = 0; d < 64; d++) s = fmaf(qreg[d], ks[j][d], s);
            s *= scale;
            if (useBias) s += __ldg(&rpb[qglob - (kt * 64 + j) + 1023]);
            sc[kk] = s;
        }

        float tmax = sc[0];
#pragma unroll
        for (int kk = 1; kk < 16; kk++) tmax = fmaxf(tmax, sc[kk]);
        tmax = fmaxf(tmax, __shfl_xor_sync(0xffffffffu, tmax, 1));
        tmax = fmaxf(tmax, __shfl_xor_sync(0xffffffffu, tmax, 2));

        float newm = fmaxf(m_i, tmax);
        float corr = expf(m_i - newm);
        l_i *= corr;
#pragma unroll
        for (int i = 0; i < 16; i++) acc[i] *= corr;
        m_i = newm;

        float psum = 0.f;
#pragma unroll
        for (int kk = 0; kk < 16; kk++) {
            float p = expf(sc[kk] - m_i);
            psum += p;
            ps[r][kk * 4 + sub] = p;
        }
        l_i += psum;
        __syncthreads();

#pragma unroll
        for (int j = 0; j < 64; j++) {
            float pj = ps[r][j];
#pragma unroll
            for (int d = 0; d < 16; d++)
                acc[d] = fmaf(pj, vs[j][sub * 16 + d], acc[d]);
        }
        __syncthreads();
    }

    l_i += __shfl_xor_sync(0xffffffffu, l_i, 1);
    l_i += __shfl_xor_sync(0xffffffffu, l_i, 2);
    float inv = 1.f / l_i;

    float* orow = out + (size_t)(b * SEQ + qglob) * DMODEL + head * HDIM + sub * 16;
#pragma unroll
    for (int i = 0; i < 4; i++) {
        float4 t = make_float4(acc[4 * i] * inv, acc[4 * i + 1] * inv,
                               acc[4 * i + 2] * inv, acc[4 * i + 3] * inv);
        *(float4*)(orow + 4 * i) = t;
    }
}

// ---------------- residual + LayerNorm (+ optional split) ----------------
__global__ __launch_bounds__(256) void ln_kernel(
    const float* __restrict__ A, const float* __restrict__ Bx,
    const float* __restrict__ g, const float* __restrict__ beta,
    float* __restrict__ out,
    __nv_bfloat16* __restrict__ hi, __nv_bfloat16* __restrict__ lo)
{
    int row = blockIdx.x, tid = threadIdx.x;
    const float4 va = ((const float4*)(A + (size_t)row * DMODEL))[tid];
    const float4 vb = ((const float4*)(Bx + (size_t)row * DMODEL))[tid];
    float x0 = va.x + vb.x, x1 = va.y + vb.y, x2 = va.z + vb.z, x3 = va.w + vb.w;

    float s = x0 + x1 + x2 + x3;
    float ss = x0 * x0 + x1 * x1 + x2 * x2 + x3 * x3;
#pragma unroll
    for (int o = 16; o > 0; o >>= 1) {
        s  += __shfl_xor_sync(0xffffffffu, s, o);
        ss += __shfl_xor_sync(0xffffffffu, ss, o);
    }
    __shared__ float sb[16];
    int warp = tid >> 5, lane = tid & 31;
    if (lane == 0) { sb[warp] = s; sb[8 + warp] = ss; }
    __syncthreads();
    if (warp == 0) {
        float s2  = (lane < 8) ? sb[lane] : 0.f;
        float ss2 = (lane < 8) ? sb[8 + lane] : 0.f;
#pragma unroll
        for (int o = 4; o > 0; o >>= 1) {
            s2  += __shfl_xor_sync(0xffffffffu, s2, o);
            ss2 += __shfl_xor_sync(0xffffffffu, ss2, o);
        }
        if (lane == 0) { sb[0] = s2; sb[8] = ss2; }
    }
    __syncthreads();
    float mu  = sb[0] * (1.f / 1024.f);
    float var = sb[8] * (1.f / 1024.f) - mu * mu;
    float rstd = rsqrtf(var + 1e-5f);

    float4 go = ((const float4*)g)[tid];
    float4 bo = ((const float4*)beta)[tid];
    float4 r4;
    r4.x = (x0 - mu) * rstd * go.x + bo.x;
    r4.y = (x1 - mu) * rstd * go.y + bo.y;
    r4.z = (x2 - mu) * rstd * go.z + bo.z;
    r4.w = (x3 - mu) * rstd * go.w + bo.w;
    ((float4*)(out + (size_t)row * DMODEL))[tid] = r4;

    if (hi) {
        size_t base = (size_t)row * DMODEL + tid * 4;
        __nv_bfloat16 h0, l0, h1, l1, h2, l2, h3, l3;
        split1(r4.x, h0, l0); split1(r4.y, h1, l1);
        split1(r4.z, h2, l2); split1(r4.w, h3, l3);
        *(__nv_bfloat162*)&hi[base]     = __nv_bfloat162(h0, h1);
        *(__nv_bfloat162*)&hi[base + 2] = __nv_bfloat162(h2, h3);
        *(__nv_bfloat162*)&lo[base]     = __nv_bfloat162(l0, l1);
        *(__nv_bfloat162*)&lo[base + 2] = __nv_bfloat162(l2, l3);
    }
}

// ---------------- orchestration ----------------
extern "C" void kernel_launch(void* const* d_in, const int* in_sizes, int n_in,
                              void* d_out, int out_size)
{
    const float* hidden = (const float*)d_in[0];
    const float* source = (const float*)d_in[1];
    const int*   tstep  = (const int*)d_in[2];
    const float* sembed = (const float*)d_in[3];
    const float* rpb    = (const float*)d_in[4];
    const float* Wqkv = (const float*)d_in[5],  *bqkv = (const float*)d_in[6];
    const float* Wo   = (const float*)d_in[7],  *bo   = (const float*)d_in[8];
    const float* Wcq  = (const float*)d_in[9],  *bcq  = (const float*)d_in[10];
    const float* Wckv = (const float*)d_in[11], *bckv = (const float*)d_in[12];
    const float* Wco  = (const float*)d_in[13], *bco  = (const float*)d_in[14];
    const float* W1   = (const float*)d_in[15], *b1   = (const float*)d_in[16];
    const float* W2   = (const float*)d_in[17], *b2   = (const float*)d_in[18];
    const float* gs = (const float*)d_in[19], *bts = (const float*)d_in[20];
    const float* gc = (const float*)d_in[21], *btc = (const float*)d_in[22];
    const float* gf = (const float*)d_in[23], *btf = (const float*)d_in[24];
    float* out = (float*)d_out;

    float *ph, *pqkv, *pattn, *pproj;
    __nv_bfloat16 *pahi, *palo, *pffhi, *pfflo, *pwhi, *pwlo;
    cudaGetSymbolAddress((void**)&ph,    g_h);
    cudaGetSymbolAddress((void**)&pqkv,  g_qkv);
    cudaGetSymbolAddress((void**)&pattn, g_attn);
    cudaGetSymbolAddress((void**)&pproj, g_proj);
    cudaGetSymbolAddress((void**)&pahi,  g_ahi);
    cudaGetSymbolAddress((void**)&palo,  g_alo);
    cudaGetSymbolAddress((void**)&pffhi, g_ffhi);
    cudaGetSymbolAddress((void**)&pfflo, g_fflo);
    cudaGetSymbolAddress((void**)&pwhi,  g_whi);
    cudaGetSymbolAddress((void**)&pwlo,  g_wlo);

    cudaFuncSetAttribute(gemm_mma<0,0>, cudaFuncAttributeMaxDynamicSharedMemorySize, SMEM_GM);
    cudaFuncSetAttribute(gemm_mma<1,1>, cudaFuncAttributeMaxDynamicSharedMemorySize, SMEM_GM);

    // weight split+transpose (every call; deterministic)
    wsplit_t<<<dim3(3072/32, 1024/32), 256>>>(Wqkv, pwhi + OFF_QKV, pwlo + OFF_QKV, 1024, 3072);
    wsplit_t<<<dim3(1024/32, 1024/32), 256>>>(Wo,   pwhi + OFF_O,   pwlo + OFF_O,   1024, 1024);
    wsplit_t<<<dim3(1024/32, 1024/32), 256>>>(Wcq,  pwhi + OFF_CQ,  pwlo + OFF_CQ,  1024, 1024);
    wsplit_t<<<dim3(2048/32, 1024/32), 256>>>(Wckv, pwhi + OFF_CKV, pwlo + OFF_CKV, 1024, 2048);
    wsplit_t<<<dim3(1024/32, 1024/32), 256>>>(Wco,  pwhi + OFF_CO,  pwlo + OFF_CO,  1024, 1024);
    wsplit_t<<<dim3(4096/32, 1024/32), 256>>>(W1,   pwhi + OFF_W1,  pwlo + OFF_W1,  1024, 4096);
    wsplit_t<<<dim3(1024/32, 4096/32), 256>>>(W2,   pwhi + OFF_W2,  pwlo + OFF_W2,  4096, 1024);

    // h0 = hidden + step_embed (also split to bf16 hi/lo)
    add_step_kernel<<<TOKENS * DMODEL / 1024, 256>>>(hidden, sembed, tstep, ph, pahi, palo);

    // qkv = h0 @ Wqkv
    gemm_mma<0,0><<<dim3(3072/128, TOKENS/128), 256, SMEM_GM>>>(
        pahi, palo, pwhi + OFF_QKV, pwlo + OFF_QKV, bqkv, pqkv, nullptr, nullptr,
        TOKENS, 3072, 1024);

    dim3 ga(SEQ / 32, NHEAD, 4);
    attn_kernel<<<ga, 128>>>(pqkv, 3 * DMODEL, pqkv, 3 * DMODEL, DMODEL, 2 * DMODEL,
                             rpb, pattn, 1);

    split_act<<<TOKENS * DMODEL / 1024, 256>>>(pattn, pahi, palo);
    gemm_mma<0,0><<<dim3(1024/128, TOKENS/128), 256, SMEM_GM>>>(
        pahi, palo, pwhi + OFF_O, pwlo + OFF_O, bo, pproj, nullptr, nullptr,
        TOKENS, 1024, 1024);
    ln_kernel<<<TOKENS, 256>>>(ph, pproj, gs, bts, ph, pahi, palo);

    gemm_mma<0,0><<<dim3(1024/128, TOKENS/128), 256, SMEM_GM>>>(
        pahi, palo, pwhi + OFF_CQ, pwlo + OFF_CQ, bcq, pattn, nullptr, nullptr,
        TOKENS, 1024, 1024);
    split_act<<<TOKENS * DMODEL / 1024, 256>>>(source, pahi, palo);
    gemm_mma<0,0><<<dim3(2048/128, TOKENS/128), 256, SMEM_GM>>>(
        pahi, palo, pwhi + OFF_CKV, pwlo + OFF_CKV, bckv, pqkv, nullptr, nullptr,
        TOKENS, 2048, 1024);
    attn_kernel<<<ga, 128>>>(pattn, DMODEL, pqkv, 2 * DMODEL, 0, DMODEL,
                             rpb, pproj, 0);

    split_act<<<TOKENS * DMODEL / 1024, 256>>>(pproj, pahi, palo);
    gemm_mma<0,0><<<dim3(1024/128, TOKENS/128), 256, SMEM_GM>>>(
        pahi, palo, pwhi + OFF_CO, pwlo + OFF_CO, bco, pattn, nullptr, nullptr,
        TOKENS, 1024, 1024);
    ln_kernel<<<TOKENS, 256>>>(ph, pattn, gc, btc, ph, pahi, palo);

    // FFN: W1 emits bf16 hi/lo directly (GELU fused), W2 consumes them
    gemm_mma<1,1><<<dim3(4096/128, TOKENS/128), 256, SMEM_GM>>>(
        pahi, palo, pwhi + OFF_W1, pwlo + OFF_W1, b1, nullptr, pffhi, pfflo,
        TOKENS, 4096, 1024);
    gemm_mma<0,0><<<dim3(1024/128, TOKENS/128), 256, SMEM_GM>>>(
        pffhi, pfflo, pwhi + OFF_W2, pwlo + OFF_W2, b2, pproj, nullptr, nullptr,
        TOKENS, 1024, 4096);
    ln_kernel<<<TOKENS, 256>>>(ph, pproj, gf, btf, out, nullptr, nullptr);
}

// round 4
// speedup vs baseline: 4.6761x; 3.0706x over previous
#include <cuda_runtime.h>
#include <cuda_bf16.h>
#include <cstdint>
#include <math.h>

#define TOKENS 4096
#define DMODEL 1024
#define SEQ    1024
#define NHEAD  16
#define HDIM   64
#define DFF_   4096

// ---------------- scratch (device globals: allocation-free) ----------------
__device__ float g_h[TOKENS * DMODEL];
__device__ float g_attn[TOKENS * DMODEL];
__device__ float g_proj[TOKENS * DMODEL];
__device__ __nv_bfloat16 g_ahi[TOKENS * DMODEL];
__device__ __nv_bfloat16 g_alo[TOKENS * DMODEL];
__device__ __nv_bfloat16 g_ffhi[TOKENS * DFF_];   // also: qkv bf16 (12.6M elems)
__device__ __nv_bfloat16 g_fflo[TOKENS * DFF_];   // also: cq bf16 (4.2M) + ckv bf16 (8.4M)
__device__ __nv_bfloat16 g_whi[16777216];
__device__ __nv_bfloat16 g_wlo[16777216];

#define OFF_QKV 0
#define OFF_O   3145728
#define OFF_CQ  4194304
#define OFF_CKV 5242880
#define OFF_CO  7340032
#define OFF_W1  8388608
#define OFF_W2  12582912

// ---------------- helpers ----------------
__device__ __forceinline__ uint32_t smem_u32(const void* p) {
    uint32_t a;
    asm("{ .reg .u64 t; cvta.to.shared.u64 t, %1; cvt.u32.u64 %0, t; }" : "=r"(a) : "l"(p));
    return a;
}
__device__ __forceinline__ void cpa16(uint32_t d, const void* g) {
    asm volatile("cp.async.cg.shared.global [%0], [%1], 16;" :: "r"(d), "l"(g));
}
#define CP_COMMIT() asm volatile("cp.async.commit_group;" ::: "memory")
#define LDSM4(r, a) \
    asm volatile("ldmatrix.sync.aligned.m8n8.x4.shared.b16 {%0,%1,%2,%3}, [%4];" \
        : "=r"((r)[0]), "=r"((r)[1]), "=r"((r)[2]), "=r"((r)[3]) : "r"(a))
#define LDSM4T(r, a) \
    asm volatile("ldmatrix.sync.aligned.m8n8.x4.trans.shared.b16 {%0,%1,%2,%3}, [%4];" \
        : "=r"((r)[0]), "=r"((r)[1]), "=r"((r)[2]), "=r"((r)[3]) : "r"(a))

__device__ __forceinline__ void mma_bf16(float* d, const uint32_t* a, const uint32_t* b) {
    asm volatile("mma.sync.aligned.m16n8k16.row.col.f32.bf16.bf16.f32 "
                 "{%0,%1,%2,%3}, {%4,%5,%6,%7}, {%8,%9}, {%0,%1,%2,%3};"
                 : "+f"(d[0]), "+f"(d[1]), "+f"(d[2]), "+f"(d[3])
                 : "r"(a[0]), "r"(a[1]), "r"(a[2]), "r"(a[3]), "r"(b[0]), "r"(b[1]));
}
__device__ __forceinline__ void split1(float x, __nv_bfloat16& h, __nv_bfloat16& l) {
    h = __float2bfloat16_rn(x);
    l = __float2bfloat16_rn(x - __bfloat162float(h));
}
__device__ __forceinline__ uint32_t packbf2(float a, float b) {
    __nv_bfloat162 t = __float22bfloat162_rn(make_float2(a, b));
    return *(uint32_t*)&t;
}

// ---------------- bf16x3 HMMA GEMM ----------------
// OUTMODE: 0 = f32 out; 1 = GELU + bf16 hi/lo out; 2 = bf16 hi out
#define STG_A_LO 16384
#define STG_B_HI 32768
#define STG_SZ   65536
#define SMEM_GM  131072

template <int ACT, int OUTMODE>
__global__ __launch_bounds__(256) void gemm_mma(
    const __nv_bfloat16* __restrict__ Ahi, const __nv_bfloat16* __restrict__ Alo,
    const __nv_bfloat16* __restrict__ Bhi, const __nv_bfloat16* __restrict__ Blo,
    const float* __restrict__ bias, float* __restrict__ C,
    __nv_bfloat16* __restrict__ Chi, __nv_bfloat16* __restrict__ Clo,
    int M, int N, int K)
{
    extern __shared__ char smem[];
    uint32_t sb = smem_u32(smem);
    int tid = threadIdx.x, lane = tid & 31, wid = tid >> 5;
    int wm = wid & 1, wn = wid >> 1;
    int bm = blockIdx.y * 128, bn = blockIdx.x * 128;

    float acc[4][4][4];
#pragma unroll
    for (int a = 0; a < 4; a++)
#pragma unroll
        for (int b = 0; b < 4; b++)
#pragma unroll
            for (int c = 0; c < 4; c++) acc[a][b][c] = 0.f;

    auto load_stage = [&](int kc, int s) {
        uint32_t base = sb + s * STG_SZ;
        const __nv_bfloat16* srcs[4] = {Ahi, Alo, Bhi, Blo};
        int rbs[4] = {bm, bm, bn, bn};
#pragma unroll
        for (int m = 0; m < 4; m++) {
            const __nv_bfloat16* src = srcs[m];
            int rb = rbs[m];
#pragma unroll
            for (int i = 0; i < 4; i++) {
                int idx = tid + i * 256;
                int row = idx >> 3, ch = idx & 7;
                uint32_t dst = base + m * 16384 + row * 128 + ((ch ^ (row & 7)) << 4);
                cpa16(dst, src + (size_t)(rb + row) * K + kc * 64 + ch * 8);
            }
        }
        CP_COMMIT();
    };

    const int NC = K >> 6;
    load_stage(0, 0);

    for (int c = 0; c < NC; c++) {
        if (c + 1 < NC) {
            load_stage(c + 1, (c + 1) & 1);
            asm volatile("cp.async.wait_group 1;" ::: "memory");
        } else {
            asm volatile("cp.async.wait_group 0;" ::: "memory");
        }
        __syncthreads();

        uint32_t aBase = sb + (c & 1) * STG_SZ;
#pragma unroll
        for (int ks = 0; ks < 4; ks++) {
            uint32_t ah[4][4], al[4][4];
#pragma unroll
            for (int mt = 0; mt < 4; mt++) {
                int row = wm * 64 + mt * 16 + (lane & 15);
                int ch = ks * 2 + (lane >> 4);
                uint32_t ad = aBase + row * 128 + ((ch ^ (row & 7)) << 4);
                LDSM4(ah[mt], ad);
                LDSM4(al[mt], ad + STG_A_LO);
            }
            uint32_t bh[2][4], bl[2][4];
#pragma unroll
            for (int nh = 0; nh < 2; nh++) {
                int row = wn * 32 + nh * 16 + (lane & 7) + ((lane >> 4) << 3);
                int ch = ks * 2 + ((lane >> 3) & 1);
                uint32_t bd = aBase + STG_B_HI + row * 128 + ((ch ^ (row & 7)) << 4);
                LDSM4(bh[nh], bd);
                LDSM4(bl[nh], bd + 16384);
            }
#pragma unroll
            for (int mt = 0; mt < 4; mt++) {
#pragma unroll
                for (int nt = 0; nt < 4; nt++) {
                    uint32_t* B1 = &bh[nt >> 1][(nt & 1) * 2];
                    uint32_t* B2 = &bl[nt >> 1][(nt & 1) * 2];
                    mma_bf16(acc[mt][nt], ah[mt], B1);
                    mma_bf16(acc[mt][nt], ah[mt], B2);
                    mma_bf16(acc[mt][nt], al[mt], B1);
                }
            }
        }
        __syncthreads();
    }

#pragma unroll
    for (int mt = 0; mt < 4; mt++) {
#pragma unroll
        for (int nt = 0; nt < 4; nt++) {
            int col = bn + wn * 32 + nt * 8 + (lane & 3) * 2;
            int r0 = bm + wm * 64 + mt * 16 + (lane >> 2);
            float bb0 = __ldg(&bias[col]), bb1 = __ldg(&bias[col + 1]);
#pragma unroll
            for (int half = 0; half < 2; half++) {
                int r = r0 + half * 8;
                float x0 = acc[mt][nt][half * 2 + 0] + bb0;
                float x1 = acc[mt][nt][half * 2 + 1] + bb1;
                if (ACT == 1) {
                    x0 = 0.5f * x0 * (1.f + erff(x0 * 0.70710678118654752f));
                    x1 = 0.5f * x1 * (1.f + erff(x1 * 0.70710678118654752f));
                }
                if (OUTMODE == 1) {
                    __nv_bfloat16 h0, l0, h1, l1;
                    split1(x0, h0, l0); split1(x1, h1, l1);
                    *(__nv_bfloat162*)&Chi[(size_t)r * N + col] = __nv_bfloat162(h0, h1);
                    *(__nv_bfloat162*)&Clo[(size_t)r * N + col] = __nv_bfloat162(l0, l1);
                } else if (OUTMODE == 2) {
                    *(__nv_bfloat162*)&Chi[(size_t)r * N + col] =
                        __float22bfloat162_rn(make_float2(x0, x1));
                } else {
                    *(float2*)&C[(size_t)r * N + col] = make_float2(x0, x1);
                }
            }
        }
    }
}

// ---------------- bf16 tensor-core flash attention ----------------
// Block: 128 queries x full key loop. 8 warps, 16 q-rows each. 64-key tiles.
// Q: bf16 [token][qs] at head*64; K/V: bf16 [token][kvs] at koff/voff + head*64.
#define ATT_SQ   0
#define ATT_SK   16384
#define ATT_SV   32768
#define ATT_RPB  49152
#define ATT_SMEM 53760

template <int BIAS>
__global__ __launch_bounds__(256) void attn_tc(
    const __nv_bfloat16* __restrict__ Qb, int qs,
    const __nv_bfloat16* __restrict__ KVb, int kvs, int koff, int voff,
    const float* __restrict__ rpb, float* __restrict__ out)
{
    extern __shared__ char smem[];
    uint32_t sb = smem_u32(smem);
    float* srpb = (float*)(smem + ATT_RPB);
    int tid = threadIdx.x, lane = tid & 31, w = tid >> 5;
    int bq = blockIdx.x, head = blockIdx.y, b = blockIdx.z;

    // rpb window: q - key + 1023 for q in [bq*128, +128), key in [0,1024)
    if (BIAS) {
        for (int i = tid; i < 1151; i += 256)
            srpb[i] = __ldg(&rpb[bq * 128 + i]);
    }

    // Q tile 128x64 bf16 -> smem (group 0, with K0/V0)
    {
        const __nv_bfloat16* qsrc = Qb + (size_t)(b * SEQ + bq * 128) * qs + head * HDIM;
#pragma unroll
        for (int i = 0; i < 4; i++) {
            int idx = tid + i * 256;
            int row = idx >> 3, ch = idx & 7;
            cpa16(sb + ATT_SQ + row * 128 + ((ch ^ (row & 7)) << 4),
                  qsrc + (size_t)row * qs + ch * 8);
        }
    }
    auto load_kv = [&](int t, int s) {
        const __nv_bfloat16* kb = KVb + (size_t)(b * SEQ + t * 64) * kvs + koff + head * HDIM;
        const __nv_bfloat16* vb = KVb + (size_t)(b * SEQ + t * 64) * kvs + voff + head * HDIM;
#pragma unroll
        for (int i = 0; i < 2; i++) {
            int idx = tid + i * 256;
            int row = idx >> 3, ch = idx & 7;
            uint32_t so = row * 128 + ((ch ^ (row & 7)) << 4) + s * 8192;
            cpa16(sb + ATT_SK + so, kb + (size_t)row * kvs + ch * 8);
            cpa16(sb + ATT_SV + so, vb + (size_t)row * kvs + ch * 8);
        }
        CP_COMMIT();
    };
    load_kv(0, 0);

    uint32_t qf[4][4];
    float O[8][4];
#pragma unroll
    for (int j = 0; j < 8; j++)
#pragma unroll
        for (int e = 0; e < 4; e++) O[j][e] = 0.f;
    float m0 = -1e30f, m1 = -1e30f, l0 = 0.f, l1 = 0.f;

    const int qo_lo = w * 16 + (lane >> 2);

    for (int t = 0; t < 16; t++) {
        __syncthreads();                       // prior tile fully consumed
        if (t + 1 < 16) {
            load_kv(t + 1, (t + 1) & 1);
            asm volatile("cp.async.wait_group 1;" ::: "memory");
        } else {
            asm volatile("cp.async.wait_group 0;" ::: "memory");
        }
        __syncthreads();

        if (t == 0) {
#pragma unroll
            for (int ks = 0; ks < 4; ks++) {
                int row = w * 16 + (lane & 15);
                int ch = ks * 2 + (lane >> 4);
                LDSM4(qf[ks], sb + ATT_SQ + row * 128 + ((ch ^ (row & 7)) << 4));
            }
        }

        uint32_t kbase = sb + ATT_SK + (t & 1) * 8192;
        uint32_t vbase = sb + ATT_SV + (t & 1) * 8192;

        // --- scores = Q K^T ---
        float sc[8][4];
#pragma unroll
        for (int j = 0; j < 8; j++)
#pragma unroll
            for (int e = 0; e < 4; e++) sc[j][e] = 0.f;
#pragma unroll
        for (int p = 0; p < 4; p++) {
#pragma unroll
            for (int ks = 0; ks < 4; ks++) {
                uint32_t kf[4];
                int row = p * 16 + (lane & 7) + ((lane >> 4) << 3);
                int ch = ks * 2 + ((lane >> 3) & 1);
                LDSM4(kf, kbase + row * 128 + ((ch ^ (row & 7)) << 4));
                mma_bf16(sc[2 * p], qf[ks], kf);
                mma_bf16(sc[2 * p + 1], qf[ks], kf + 2);
            }
        }

        // --- scale + bias + online softmax ---
        float mx0 = -1e30f, mx1 = -1e30f;
#pragma unroll
        for (int j = 0; j < 8; j++) {
            int keyb = t * 64 + 8 * j + 2 * (lane & 3);
#pragma unroll
            for (int e = 0; e < 4; e++) {
                float s = sc[j][e] * 0.125f;
                if (BIAS) {
                    int qo = qo_lo + (e >> 1) * 8;
                    s += srpb[qo - (keyb + (e & 1)) + 1023];
                }
                sc[j][e] = s;
                if ((e >> 1) == 0) mx0 = fmaxf(mx0, s); else mx1 = fmaxf(mx1, s);
            }
        }
        mx0 = fmaxf(mx0, __shfl_xor_sync(0xffffffffu, mx0, 1));
        mx0 = fmaxf(mx0, __shfl_xor_sync(0xffffffffu, mx0, 2));
        mx1 = fmaxf(mx1, __shfl_xor_sync(0xffffffffu, mx1, 1));
        mx1 = fmaxf(mx1, __shfl_xor_sync(0xffffffffu, mx1, 2));

        float nm0 = fmaxf(m0, mx0), nm1 = fmaxf(m1, mx1);
        float cr0 = expf(m0 - nm0), cr1 = expf(m1 - nm1);
        m0 = nm0; m1 = nm1;
        l0 *= cr0; l1 *= cr1;
#pragma unroll
        for (int j = 0; j < 8; j++) {
            O[j][0] *= cr0; O[j][1] *= cr0;
            O[j][2] *= cr1; O[j][3] *= cr1;
        }
        float ps0 = 0.f, ps1 = 0.f;
#pragma unroll
        for (int j = 0; j < 8; j++) {
            sc[j][0] = expf(sc[j][0] - m0); ps0 += sc[j][0];
            sc[j][1] = expf(sc[j][1] - m0); ps0 += sc[j][1];
            sc[j][2] = expf(sc[j][2] - m1); ps1 += sc[j][2];
            sc[j][3] = expf(sc[j][3] - m1); ps1 += sc[j][3];
        }
        l0 += ps0; l1 += ps1;

        // --- O += P V ---
#pragma unroll
        for (int ks = 0; ks < 4; ks++) {
            uint32_t a[4];
            a[0] = packbf2(sc[2 * ks][0], sc[2 * ks][1]);
            a[1] = packbf2(sc[2 * ks][2], sc[2 * ks][3]);
            a[2] = packbf2(sc[2 * ks + 1][0], sc[2 * ks + 1][1]);
            a[3] = packbf2(sc[2 * ks + 1][2], sc[2 * ks + 1][3]);
#pragma unroll
            for (int nc = 0; nc < 4; nc++) {
                uint32_t vf[4];
                int row = ks * 16 + (lane & 15);
                int ch = nc * 2 + (lane >> 4);
                LDSM4T(vf, vbase + row * 128 + ((ch ^ (row & 7)) << 4));
                mma_bf16(O[2 * nc], a, vf);
                mma_bf16(O[2 * nc + 1], a, vf + 2);
            }
        }
    }

    l0 += __shfl_xor_sync(0xffffffffu, l0, 1);
    l0 += __shfl_xor_sync(0xffffffffu, l0, 2);
    l1 += __shfl_xor_sync(0xffffffffu, l1, 1);
    l1 += __shfl_xor_sync(0xffffffffu, l1, 2);
    float i0 = 1.f / l0, i1 = 1.f / l1;

    int tok_lo = b * SEQ + bq * 128 + qo_lo;
    float* o_lo = out + (size_t)tok_lo * DMODEL + head * HDIM + 2 * (lane & 3);
    float* o_hi = o_lo + 8 * DMODEL;
#pragma unroll
    for (int j = 0; j < 8; j++) {
        *(float2*)(o_lo + 8 * j) = make_float2(O[j][0] * i0, O[j][1] * i0);
        *(float2*)(o_hi + 8 * j) = make_float2(O[j][2] * i1, O[j][3] * i1);
    }
}

// ---------------- weight split+transpose: W[K][N] -> hi/lo [N][K] ----------------
__global__ __launch_bounds__(256) void wsplit_t(
    const float* __restrict__ W, __nv_bfloat16* __restrict__ hi,
    __nv_bfloat16* __restrict__ lo, int K, int N)
{
    __shared__ float s[32][33];
    int tx = threadIdx.x & 31, ty = threadIdx.x >> 5;
    int n0 = blockIdx.x * 32, k0 = blockIdx.y * 32;
#pragma unroll
    for (int i = 0; i < 4; i++)
        s[ty + 8 * i][tx] = W[(size_t)(k0 + ty + 8 * i) * N + n0 + tx];
    __syncthreads();
#pragma unroll
    for (int i = 0; i < 4; i++) {
        int n = ty + 8 * i;
        float v = s[tx][n];
        __nv_bfloat16 h, l;
        split1(v, h, l);
        hi[(size_t)(n0 + n) * K + k0 + tx] = h;
        lo[(size_t)(n0 + n) * K + k0 + tx] = l;
    }
}

// ---------------- activation split ----------------
__global__ void split_act(const float* __restrict__ in,
                          __nv_bfloat16* __restrict__ hi,
                          __nv_bfloat16* __restrict__ lo)
{
    int idx = blockIdx.x * 256 + threadIdx.x;
    float4 v = ((const float4*)in)[idx];
    __nv_bfloat16 h0, l0, h1, l1, h2, l2, h3, l3;
    split1(v.x, h0, l0); split1(v.y, h1, l1);
    split1(v.z, h2, l2); split1(v.w, h3, l3);
    ((__nv_bfloat162*)hi)[idx * 2]     = __nv_bfloat162(h0, h1);
    ((__nv_bfloat162*)hi)[idx * 2 + 1] = __nv_bfloat162(h2, h3);
    ((__nv_bfloat162*)lo)[idx * 2]     = __nv_bfloat162(l0, l1);
    ((__nv_bfloat162*)lo)[idx * 2 + 1] = __nv_bfloat162(l2, l3);
}

// ---------------- step-embed add (+split) ----------------
__global__ void add_step_kernel(const float* __restrict__ hidden,
                                const float* __restrict__ se,
                                const int* __restrict__ ts,
                                float* __restrict__ out,
                                __nv_bfloat16* __restrict__ hi,
                                __nv_bfloat16* __restrict__ lo)
{
    int idx = blockIdx.x * 256 + threadIdx.x;
    int c = ts[0];
    if (c > 19) c = 19;
    float4 h = ((const float4*)hidden)[idx];
    float4 s = ((const float4*)(se + c * DMODEL))[idx & 255];
    float4 o = make_float4(h.x + s.x, h.y + s.y, h.z + s.z, h.w + s.w);
    ((float4*)out)[idx] = o;
    __nv_bfloat16 h0, l0, h1, l1, h2, l2, h3, l3;
    split1(o.x, h0, l0); split1(o.y, h1, l1);
    split1(o.z, h2, l2); split1(o.w, h3, l3);
    ((__nv_bfloat162*)hi)[idx * 2]     = __nv_bfloat162(h0, h1);
    ((__nv_bfloat162*)hi)[idx * 2 + 1] = __nv_bfloat162(h2, h3);
    ((__nv_bfloat162*)lo)[idx * 2]     = __nv_bfloat162(l0, l1);
    ((__nv_bfloat162*)lo)[idx * 2 + 1] = __nv_bfloat162(l2, l3);
}

// ---------------- residual + LayerNorm (+ optional split) ----------------
__global__ __launch_bounds__(256) void ln_kernel(
    const float* __restrict__ A, const float* __restrict__ Bx,
    const float* __restrict__ g, const float* __restrict__ beta,
    float* __restrict__ out,
    __nv_bfloat16* __restrict__ hi, __nv_bfloat16* __restrict__ lo)
{
    int row = blockIdx.x, tid = threadIdx.x;
    const float4 va = ((const float4*)(A + (size_t)row * DMODEL))[tid];
    const float4 vb = ((const float4*)(Bx + (size_t)row * DMODEL))[tid];
    float x0 = va.x + vb.x, x1 = va.y + vb.y, x2 = va.z + vb.z, x3 = va.w + vb.w;

    float s = x0 + x1 + x2 + x3;
    float ss = x0 * x0 + x1 * x1 + x2 * x2 + x3 * x3;
#pragma unroll
    for (int o = 16; o > 0; o >>= 1) {
        s  += __shfl_xor_sync(0xffffffffu, s, o);
        ss += __shfl_xor_sync(0xffffffffu, ss, o);
    }
    __shared__ float sb[16];
    int warp = tid >> 5, lane = tid & 31;
    if (lane == 0) { sb[warp] = s; sb[8 + warp] = ss; }
    __syncthreads();
    if (warp == 0) {
        float s2  = (lane < 8) ? sb[lane] : 0.f;
        float ss2 = (lane < 8) ? sb[8 + lane] : 0.f;
#pragma unroll
        for (int o = 4; o > 0; o >>= 1) {
            s2  += __shfl_xor_sync(0xffffffffu, s2, o);
            ss2 += __shfl_xor_sync(0xffffffffu, ss2, o);
        }
        if (lane == 0) { sb[0] = s2; sb[8] = ss2; }
    }
    __syncthreads();
    float mu  = sb[0] * (1.f / 1024.f);
    float var = sb[8] * (1.f / 1024.f) - mu * mu;
    float rstd = rsqrtf(var + 1e-5f);

    float4 go = ((const float4*)g)[tid];
    float4 bo = ((const float4*)beta)[tid];
    float4 r4;
    r4.x = (x0 - mu) * rstd * go.x + bo.x;
    r4.y = (x1 - mu) * rstd * go.y + bo.y;
    r4.z = (x2 - mu) * rstd * go.z + bo.z;
    r4.w = (x3 - mu) * rstd * go.w + bo.w;
    ((float4*)(out + (size_t)row * DMODEL))[tid] = r4;

    if (hi) {
        size_t base = (size_t)row * DMODEL + tid * 4;
        __nv_bfloat16 h0, l0, h1, l1, h2, l2, h3, l3;
        split1(r4.x, h0, l0); split1(r4.y, h1, l1);
        split1(r4.z, h2, l2); split1(r4.w, h3, l3);
        *(__nv_bfloat162*)&hi[base]     = __nv_bfloat162(h0, h1);
        *(__nv_bfloat162*)&hi[base + 2] = __nv_bfloat162(h2, h3);
        *(__nv_bfloat162*)&lo[base]     = __nv_bfloat162(l0, l1);
        *(__nv_bfloat162*)&lo[base + 2] = __nv_bfloat162(l2, l3);
    }
}

// ---------------- orchestration ----------------
extern "C" void kernel_launch(void* const* d_in, const int* in_sizes, int n_in,
                              void* d_out, int out_size)
{
    const float* hidden = (const float*)d_in[0];
    const float* source = (const float*)d_in[1];
    const int*   tstep  = (const int*)d_in[2];
    const float* sembed = (const float*)d_in[3];
    const float* rpb    = (const float*)d_in[4];
    const float* Wqkv = (const float*)d_in[5],  *bqkv = (const float*)d_in[6];
    const float* Wo   = (const float*)d_in[7],  *bo   = (const float*)d_in[8];
    const float* Wcq  = (const float*)d_in[9],  *bcq  = (const float*)d_in[10];
    const float* Wckv = (const float*)d_in[11], *bckv = (const float*)d_in[12];
    const float* Wco  = (const float*)d_in[13], *bco  = (const float*)d_in[14];
    const float* W1   = (const float*)d_in[15], *b1   = (const float*)d_in[16];
    const float* W2   = (const float*)d_in[17], *b2   = (const float*)d_in[18];
    const float* gs = (const float*)d_in[19], *bts = (const float*)d_in[20];
    const float* gc = (const float*)d_in[21], *btc = (const float*)d_in[22];
    const float* gf = (const float*)d_in[23], *btf = (const float*)d_in[24];
    float* out = (float*)d_out;

    float *ph, *pattn, *pproj;
    __nv_bfloat16 *pahi, *palo, *pffhi, *pfflo, *pwhi, *pwlo;
    cudaGetSymbolAddress((void**)&ph,    g_h);
    cudaGetSymbolAddress((void**)&pattn, g_attn);
    cudaGetSymbolAddress((void**)&pproj, g_proj);
    cudaGetSymbolAddress((void**)&pahi,  g_ahi);
    cudaGetSymbolAddress((void**)&palo,  g_alo);
    cudaGetSymbolAddress((void**)&pffhi, g_ffhi);
    cudaGetSymbolAddress((void**)&pfflo, g_fflo);
    cudaGetSymbolAddress((void**)&pwhi,  g_whi);
    cudaGetSymbolAddress((void**)&pwlo,  g_wlo);

    __nv_bfloat16* pqkvb = pffhi;              // qkv bf16 [4096][3072]
    __nv_bfloat16* pcqb  = pfflo;              // cq  bf16 [4096][1024]
    __nv_bfloat16* pckvb = pfflo + 4194304;    // ckv bf16 [4096][2048]

    cudaFuncSetAttribute(gemm_mma<0,0>, cudaFuncAttributeMaxDynamicSharedMemorySize, SMEM_GM);
    cudaFuncSetAttribute(gemm_mma<1,1>, cudaFuncAttributeMaxDynamicSharedMemorySize, SMEM_GM);
    cudaFuncSetAttribute(gemm_mma<0,2>, cudaFuncAttributeMaxDynamicSharedMemorySize, SMEM_GM);
    cudaFuncSetAttribute(attn_tc<0>, cudaFuncAttributeMaxDynamicSharedMemorySize, ATT_SMEM);
    cudaFuncSetAttribute(attn_tc<1>, cudaFuncAttributeMaxDynamicSharedMemorySize, ATT_SMEM);

    // weight split+transpose
    wsplit_t<<<dim3(3072/32, 1024/32), 256>>>(Wqkv, pwhi + OFF_QKV, pwlo + OFF_QKV, 1024, 3072);
    wsplit_t<<<dim3(1024/32, 1024/32), 256>>>(Wo,   pwhi + OFF_O,   pwlo + OFF_O,   1024, 1024);
    wsplit_t<<<dim3(1024/32, 1024/32), 256>>>(Wcq,  pwhi + OFF_CQ,  pwlo + OFF_CQ,  1024, 1024);
    wsplit_t<<<dim3(2048/32, 1024/32), 256>>>(Wckv, pwhi + OFF_CKV, pwlo + OFF_CKV, 1024, 2048);
    wsplit_t<<<dim3(1024/32, 1024/32), 256>>>(Wco,  pwhi + OFF_CO,  pwlo + OFF_CO,  1024, 1024);
    wsplit_t<<<dim3(4096/32, 1024/32), 256>>>(W1,   pwhi + OFF_W1,  pwlo + OFF_W1,  1024, 4096);
    wsplit_t<<<dim3(1024/32, 4096/32), 256>>>(W2,   pwhi + OFF_W2,  pwlo + OFF_W2,  4096, 1024);

    add_step_kernel<<<TOKENS * DMODEL / 1024, 256>>>(hidden, sembed, tstep, ph, pahi, palo);

    // qkv = h0 @ Wqkv -> bf16
    gemm_mma<0,2><<<dim3(3072/128, TOKENS/128), 256, SMEM_GM>>>(
        pahi, palo, pwhi + OFF_QKV, pwlo + OFF_QKV, bqkv, nullptr, pqkvb, nullptr,
        TOKENS, 3072, 1024);

    dim3 ga(SEQ / 128, NHEAD, 4);
    attn_tc<1><<<ga, 256, ATT_SMEM>>>(pqkvb, 3072, pqkvb, 3072, 1024, 2048, rpb, pattn);

    split_act<<<TOKENS * DMODEL / 1024, 256>>>(pattn, pahi, palo);
    gemm_mma<0,0><<<dim3(1024/128, TOKENS/128), 256, SMEM_GM>>>(
        pahi, palo, pwhi + OFF_O, pwlo + OFF_O, bo, pproj, nullptr, nullptr,
        TOKENS, 1024, 1024);
    ln_kernel<<<TOKENS, 256>>>(ph, pproj, gs, bts, ph, pahi, palo);

    gemm_mma<0,2><<<dim3(1024/128, TOKENS/128), 256, SMEM_GM>>>(
        pahi, palo, pwhi + OFF_CQ, pwlo + OFF_CQ, bcq, nullptr, pcqb, nullptr,
        TOKENS, 1024, 1024);
    split_act<<<TOKENS * DMODEL / 1024, 256>>>(source, pahi, palo);
    gemm_mma<0,2><<<dim3(2048/128, TOKENS/128), 256, SMEM_GM>>>(
        pahi, palo, pwhi + OFF_CKV, pwlo + OFF_CKV, bckv, nullptr, pckvb, nullptr,
        TOKENS, 2048, 1024);

    attn_tc<0><<<ga, 256, ATT_SMEM>>>(pcqb, 1024, pckvb, 2048, 0, 1024, rpb, pproj);

    // NOTE: cq GEMM consumed g_ahi/g_alo of LN(self); re-split h for Wco input? No:
    // Wco input is cross-attn output pproj.
    split_act<<<TOKENS * DMODEL / 1024, 256>>>(pproj, pahi, palo);
    gemm_mma<0,0><<<dim3(1024/128, TOKENS/128), 256, SMEM_GM>>>(
        pahi, palo, pwhi + OFF_CO, pwlo + OFF_CO, bco, pattn, nullptr, nullptr,
        TOKENS, 1024, 1024);
    ln_kernel<<<TOKENS, 256>>>(ph, pattn, gc, btc, ph, pahi, palo);

    gemm_mma<1,1><<<dim3(4096/128, TOKENS/128), 256, SMEM_GM>>>(
        pahi, palo, pwhi + OFF_W1, pwlo + OFF_W1, b1, nullptr, pffhi, pfflo,
        TOKENS, 4096, 1024);
    gemm_mma<0,0><<<dim3(1024/128, TOKENS/128), 256, SMEM_GM>>>(
        pffhi, pfflo, pwhi + OFF_W2, pwlo + OFF_W2, b2, pproj, nullptr, nullptr,
        TOKENS, 1024, 4096);
    ln_kernel<<<TOKENS, 256>>>(ph, pproj, gf, btf, out, nullptr, nullptr);
}

// round 5
// speedup vs baseline: 6.1647x; 1.3183x over previous
#include <cuda_runtime.h>
#include <cuda_bf16.h>
#include <cstdint>
#include <math.h>

#define TOKENS 4096
#define DMODEL 1024
#define SEQ    1024
#define NHEAD  16
#define HDIM   64
#define DFF_   4096

// ---------------- scratch (device globals: allocation-free) ----------------
__device__ float g_h[TOKENS * DMODEL];
__device__ float g_attn[TOKENS * DMODEL];
__device__ float g_proj[TOKENS * DMODEL];
__device__ __nv_bfloat16 g_ahi[TOKENS * DMODEL];
__device__ __nv_bfloat16 g_alo[TOKENS * DMODEL];
__device__ __nv_bfloat16 g_ffhi[TOKENS * DFF_];   // also: qkv bf16
__device__ __nv_bfloat16 g_fflo[TOKENS * DFF_];   // also: cq bf16 + ckv bf16
__device__ __nv_bfloat16 g_whi[16777216];
__device__ __nv_bfloat16 g_wlo[16777216];

#define OFF_QKV 0
#define OFF_O   3145728
#define OFF_CQ  4194304
#define OFF_CKV 5242880
#define OFF_CO  7340032
#define OFF_W1  8388608
#define OFF_W2  12582912

// ---------------- helpers ----------------
__device__ __forceinline__ uint32_t smem_u32(const void* p) {
    uint32_t a;
    asm("{ .reg .u64 t; cvta.to.shared.u64 t, %1; cvt.u32.u64 %0, t; }" : "=r"(a) : "l"(p));
    return a;
}
__device__ __forceinline__ void cpa16(uint32_t d, const void* g) {
    asm volatile("cp.async.cg.shared.global [%0], [%1], 16;" :: "r"(d), "l"(g));
}
#define CP_COMMIT() asm volatile("cp.async.commit_group;" ::: "memory")
#define LDSM4(r, a) \
    asm volatile("ldmatrix.sync.aligned.m8n8.x4.shared.b16 {%0,%1,%2,%3}, [%4];" \
        : "=r"((r)[0]), "=r"((r)[1]), "=r"((r)[2]), "=r"((r)[3]) : "r"(a))
#define LDSM4T(r, a) \
    asm volatile("ldmatrix.sync.aligned.m8n8.x4.trans.shared.b16 {%0,%1,%2,%3}, [%4];" \
        : "=r"((r)[0]), "=r"((r)[1]), "=r"((r)[2]), "=r"((r)[3]) : "r"(a))

__device__ __forceinline__ void mma_bf16(float* d, const uint32_t* a, const uint32_t* b) {
    asm volatile("mma.sync.aligned.m16n8k16.row.col.f32.bf16.bf16.f32 "
                 "{%0,%1,%2,%3}, {%4,%5,%6,%7}, {%8,%9}, {%0,%1,%2,%3};"
                 : "+f"(d[0]), "+f"(d[1]), "+f"(d[2]), "+f"(d[3])
                 : "r"(a[0]), "r"(a[1]), "r"(a[2]), "r"(a[3]), "r"(b[0]), "r"(b[1]));
}
__device__ __forceinline__ void split1(float x, __nv_bfloat16& h, __nv_bfloat16& l) {
    h = __float2bfloat16_rn(x);
    l = __float2bfloat16_rn(x - __bfloat162float(h));
}
__device__ __forceinline__ uint32_t packbf2(float a, float b) {
    __nv_bfloat162 t = __float22bfloat162_rn(make_float2(a, b));
    return *(uint32_t*)&t;
}

// ---------------- bf16 multi-pass HMMA GEMM ----------------
// PASSES: 1 = AhiBhi; 2 = +AhiBlo; 3 = +AloBhi
// OUTMODE: 0 = f32 out; 1 = GELU + bf16 hi/lo out; 2 = bf16 hi out
#define STG_A_LO 16384
#define STG_B_HI 32768
#define STG_SZ   65536
#define SMEM_GM  131072

template <int PASSES, int ACT, int OUTMODE>
__global__ __launch_bounds__(256) void gemm_mma(
    const __nv_bfloat16* __restrict__ Ahi, const __nv_bfloat16* __restrict__ Alo,
    const __nv_bfloat16* __restrict__ Bhi, const __nv_bfloat16* __restrict__ Blo,
    const float* __restrict__ bias, float* __restrict__ C,
    __nv_bfloat16* __restrict__ Chi, __nv_bfloat16* __restrict__ Clo,
    int M, int N, int K)
{
    extern __shared__ char smem[];
    uint32_t sb = smem_u32(smem);
    int tid = threadIdx.x, lane = tid & 31, wid = tid >> 5;
    int wm = wid & 1, wn = wid >> 1;
    int bm = blockIdx.y * 128, bn = blockIdx.x * 128;

    float acc[4][4][4];
#pragma unroll
    for (int a = 0; a < 4; a++)
#pragma unroll
        for (int b = 0; b < 4; b++)
#pragma unroll
            for (int c = 0; c < 4; c++) acc[a][b][c] = 0.f;

    auto load_stage = [&](int kc, int s) {
        uint32_t base = sb + s * STG_SZ;
        const __nv_bfloat16* srcs[4] = {Ahi, Alo, Bhi, Blo};
        int rbs[4] = {bm, bm, bn, bn};
#pragma unroll
        for (int m = 0; m < 4; m++) {
            if (m == 1 && PASSES < 3) continue;   // Alo only for 3-pass
            if (m == 3 && PASSES < 2) continue;   // Blo only for >=2-pass
            const __nv_bfloat16* src = srcs[m];
            int rb = rbs[m];
#pragma unroll
            for (int i = 0; i < 4; i++) {
                int idx = tid + i * 256;
                int row = idx >> 3, ch = idx & 7;
                uint32_t dst = base + m * 16384 + row * 128 + ((ch ^ (row & 7)) << 4);
                cpa16(dst, src + (size_t)(rb + row) * K + kc * 64 + ch * 8);
            }
        }
        CP_COMMIT();
    };

    const int NC = K >> 6;
    load_stage(0, 0);

    for (int c = 0; c < NC; c++) {
        if (c + 1 < NC) {
            load_stage(c + 1, (c + 1) & 1);
            asm volatile("cp.async.wait_group 1;" ::: "memory");
        } else {
            asm volatile("cp.async.wait_group 0;" ::: "memory");
        }
        __syncthreads();

        uint32_t aBase = sb + (c & 1) * STG_SZ;
#pragma unroll
        for (int ks = 0; ks < 4; ks++) {
            uint32_t ah[4][4], al[4][4];
#pragma unroll
            for (int mt = 0; mt < 4; mt++) {
                int row = wm * 64 + mt * 16 + (lane & 15);
                int ch = ks * 2 + (lane >> 4);
                uint32_t ad = aBase + row * 128 + ((ch ^ (row & 7)) << 4);
                LDSM4(ah[mt], ad);
                if (PASSES >= 3) LDSM4(al[mt], ad + STG_A_LO);
            }
            uint32_t bh[2][4], bl[2][4];
#pragma unroll
            for (int nh = 0; nh < 2; nh++) {
                int row = wn * 32 + nh * 16 + (lane & 7) + ((lane >> 4) << 3);
                int ch = ks * 2 + ((lane >> 3) & 1);
                uint32_t bd = aBase + STG_B_HI + row * 128 + ((ch ^ (row & 7)) << 4);
                LDSM4(bh[nh], bd);
                if (PASSES >= 2) LDSM4(bl[nh], bd + 16384);
            }
#pragma unroll
            for (int mt = 0; mt < 4; mt++) {
#pragma unroll
                for (int nt = 0; nt < 4; nt++) {
                    uint32_t* B1 = &bh[nt >> 1][(nt & 1) * 2];
                    mma_bf16(acc[mt][nt], ah[mt], B1);
                    if (PASSES >= 2) {
                        uint32_t* B2 = &bl[nt >> 1][(nt & 1) * 2];
                        mma_bf16(acc[mt][nt], ah[mt], B2);
                    }
                    if (PASSES >= 3) mma_bf16(acc[mt][nt], al[mt], B1);
                }
            }
        }
        __syncthreads();
    }

#pragma unroll
    for (int mt = 0; mt < 4; mt++) {
#pragma unroll
        for (int nt = 0; nt < 4; nt++) {
            int col = bn + wn * 32 + nt * 8 + (lane & 3) * 2;
            int r0 = bm + wm * 64 + mt * 16 + (lane >> 2);
            float bb0 = __ldg(&bias[col]), bb1 = __ldg(&bias[col + 1]);
#pragma unroll
            for (int half = 0; half < 2; half++) {
                int r = r0 + half * 8;
                float x0 = acc[mt][nt][half * 2 + 0] + bb0;
                float x1 = acc[mt][nt][half * 2 + 1] + bb1;
                if (ACT == 1) {
                    x0 = 0.5f * x0 * (1.f + erff(x0 * 0.70710678118654752f));
                    x1 = 0.5f * x1 * (1.f + erff(x1 * 0.70710678118654752f));
                }
                if (OUTMODE == 1) {
                    __nv_bfloat16 h0, l0, h1, l1;
                    split1(x0, h0, l0); split1(x1, h1, l1);
                    *(__nv_bfloat162*)&Chi[(size_t)r * N + col] = __nv_bfloat162(h0, h1);
                    *(__nv_bfloat162*)&Clo[(size_t)r * N + col] = __nv_bfloat162(l0, l1);
                } else if (OUTMODE == 2) {
                    *(__nv_bfloat162*)&Chi[(size_t)r * N + col] =
                        __float22bfloat162_rn(make_float2(x0, x1));
                } else {
                    *(float2*)&C[(size_t)r * N + col] = make_float2(x0, x1);
                }
            }
        }
    }
}

// ---------------- bf16 tensor-core flash attention (bf16 hi/lo output) ------
#define ATT_SQ   0
#define ATT_SK   16384
#define ATT_SV   32768
#define ATT_RPB  49152
#define ATT_SMEM 53760

template <int BIAS>
__global__ __launch_bounds__(256) void attn_tc(
    const __nv_bfloat16* __restrict__ Qb, int qs,
    const __nv_bfloat16* __restrict__ KVb, int kvs, int koff, int voff,
    const float* __restrict__ rpb,
    __nv_bfloat16* __restrict__ Ohi, __nv_bfloat16* __restrict__ Olo)
{
    extern __shared__ char smem[];
    uint32_t sb = smem_u32(smem);
    float* srpb = (float*)(smem + ATT_RPB);
    int tid = threadIdx.x, lane = tid & 31, w = tid >> 5;
    int bq = blockIdx.x, head = blockIdx.y, b = blockIdx.z;

    if (BIAS) {
        for (int i = tid; i < 1151; i += 256)
            srpb[i] = __ldg(&rpb[bq * 128 + i]);
    }

    {
        const __nv_bfloat16* qsrc = Qb + (size_t)(b * SEQ + bq * 128) * qs + head * HDIM;
#pragma unroll
        for (int i = 0; i < 4; i++) {
            int idx = tid + i * 256;
            int row = idx >> 3, ch = idx & 7;
            cpa16(sb + ATT_SQ + row * 128 + ((ch ^ (row & 7)) << 4),
                  qsrc + (size_t)row * qs + ch * 8);
        }
    }
    auto load_kv = [&](int t, int s) {
        const __nv_bfloat16* kb = KVb + (size_t)(b * SEQ + t * 64) * kvs + koff + head * HDIM;
        const __nv_bfloat16* vb = KVb + (size_t)(b * SEQ + t * 64) * kvs + voff + head * HDIM;
#pragma unroll
        for (int i = 0; i < 2; i++) {
            int idx = tid + i * 256;
            int row = idx >> 3, ch = idx & 7;
            uint32_t so = row * 128 + ((ch ^ (row & 7)) << 4) + s * 8192;
            cpa16(sb + ATT_SK + so, kb + (size_t)row * kvs + ch * 8);
            cpa16(sb + ATT_SV + so, vb + (size_t)row * kvs + ch * 8);
        }
        CP_COMMIT();
    };
    load_kv(0, 0);

    uint32_t qf[4][4];
    float O[8][4];
#pragma unroll
    for (int j = 0; j < 8; j++)
#pragma unroll
        for (int e = 0; e < 4; e++) O[j][e] = 0.f;
    float m0 = -1e30f, m1 = -1e30f, l0 = 0.f, l1 = 0.f;

    const int qo_lo = w * 16 + (lane >> 2);

    for (int t = 0; t < 16; t++) {
        __syncthreads();
        if (t + 1 < 16) {
            load_kv(t + 1, (t + 1) & 1);
            asm volatile("cp.async.wait_group 1;" ::: "memory");
        } else {
            asm volatile("cp.async.wait_group 0;" ::: "memory");
        }
        __syncthreads();

        if (t == 0) {
#pragma unroll
            for (int ks = 0; ks < 4; ks++) {
                int row = w * 16 + (lane & 15);
                int ch = ks * 2 + (lane >> 4);
                LDSM4(qf[ks], sb + ATT_SQ + row * 128 + ((ch ^ (row & 7)) << 4));
            }
        }

        uint32_t kbase = sb + ATT_SK + (t & 1) * 8192;
        uint32_t vbase = sb + ATT_SV + (t & 1) * 8192;

        float sc[8][4];
#pragma unroll
        for (int j = 0; j < 8; j++)
#pragma unroll
            for (int e = 0; e < 4; e++) sc[j][e] = 0.f;
#pragma unroll
        for (int p = 0; p < 4; p++) {
#pragma unroll
            for (int ks = 0; ks < 4; ks++) {
                uint32_t kf[4];
                int row = p * 16 + (lane & 7) + ((lane >> 4) << 3);
                int ch = ks * 2 + ((lane >> 3) & 1);
                LDSM4(kf, kbase + row * 128 + ((ch ^ (row & 7)) << 4));
                mma_bf16(sc[2 * p], qf[ks], kf);
                mma_bf16(sc[2 * p + 1], qf[ks], kf + 2);
            }
        }

        float mx0 = -1e30f, mx1 = -1e30f;
#pragma unroll
        for (int j = 0; j < 8; j++) {
            int keyb = t * 64 + 8 * j + 2 * (lane & 3);
#pragma unroll
            for (int e = 0; e < 4; e++) {
                float s = sc[j][e] * 0.125f;
                if (BIAS) {
                    int qo = qo_lo + (e >> 1) * 8;
                    s += srpb[qo - (keyb + (e & 1)) + 1023];
                }
                sc[j][e] = s;
                if ((e >> 1) == 0) mx0 = fmaxf(mx0, s); else mx1 = fmaxf(mx1, s);
            }
        }
        mx0 = fmaxf(mx0, __shfl_xor_sync(0xffffffffu, mx0, 1));
        mx0 = fmaxf(mx0, __shfl_xor_sync(0xffffffffu, mx0, 2));
        mx1 = fmaxf(mx1, __shfl_xor_sync(0xffffffffu, mx1, 1));
        mx1 = fmaxf(mx1, __shfl_xor_sync(0xffffffffu, mx1, 2));

        float nm0 = fmaxf(m0, mx0), nm1 = fmaxf(m1, mx1);
        float cr0 = __expf(m0 - nm0), cr1 = __expf(m1 - nm1);
        m0 = nm0; m1 = nm1;
        l0 *= cr0; l1 *= cr1;
#pragma unroll
        for (int j = 0; j < 8; j++) {
            O[j][0] *= cr0; O[j][1] *= cr0;
            O[j][2] *= cr1; O[j][3] *= cr1;
        }
        float ps0 = 0.f, ps1 = 0.f;
#pragma unroll
        for (int j = 0; j < 8; j++) {
            sc[j][0] = __expf(sc[j][0] - m0); ps0 += sc[j][0];
            sc[j][1] = __expf(sc[j][1] - m0); ps0 += sc[j][1];
            sc[j][2] = __expf(sc[j][2] - m1); ps1 += sc[j][2];
            sc[j][3] = __expf(sc[j][3] - m1); ps1 += sc[j][3];
        }
        l0 += ps0; l1 += ps1;

#pragma unroll
        for (int ks = 0; ks < 4; ks++) {
            uint32_t a[4];
            a[0] = packbf2(sc[2 * ks][0], sc[2 * ks][1]);
            a[1] = packbf2(sc[2 * ks][2], sc[2 * ks][3]);
            a[2] = packbf2(sc[2 * ks + 1][0], sc[2 * ks + 1][1]);
            a[3] = packbf2(sc[2 * ks + 1][2], sc[2 * ks + 1][3]);
#pragma unroll
            for (int nc = 0; nc < 4; nc++) {
                uint32_t vf[4];
                int row = ks * 16 + (lane & 15);
                int ch = nc * 2 + (lane >> 4);
                LDSM4T(vf, vbase + row * 128 + ((ch ^ (row & 7)) << 4));
                mma_bf16(O[2 * nc], a, vf);
                mma_bf16(O[2 * nc + 1], a, vf + 2);
            }
        }
    }

    l0 += __shfl_xor_sync(0xffffffffu, l0, 1);
    l0 += __shfl_xor_sync(0xffffffffu, l0, 2);
    l1 += __shfl_xor_sync(0xffffffffu, l1, 1);
    l1 += __shfl_xor_sync(0xffffffffu, l1, 2);
    float i0 = 1.f / l0, i1 = 1.f / l1;

    int tok_lo = b * SEQ + bq * 128 + qo_lo;
    size_t base_lo = (size_t)tok_lo * DMODEL + head * HDIM + 2 * (lane & 3);
    size_t base_hi = base_lo + 8 * DMODEL;
#pragma unroll
    for (int j = 0; j < 8; j++) {
        float x0 = O[j][0] * i0, x1 = O[j][1] * i0;
        float y0 = O[j][2] * i1, y1 = O[j][3] * i1;
        __nv_bfloat16 h0, l0b, h1, l1b;
        split1(x0, h0, l0b); split1(x1, h1, l1b);
        *(__nv_bfloat162*)&Ohi[base_lo + 8 * j] = __nv_bfloat162(h0, h1);
        *(__nv_bfloat162*)&Olo[base_lo + 8 * j] = __nv_bfloat162(l0b, l1b);
        split1(y0, h0, l0b); split1(y1, h1, l1b);
        *(__nv_bfloat162*)&Ohi[base_hi + 8 * j] = __nv_bfloat162(h0, h1);
        *(__nv_bfloat162*)&Olo[base_hi + 8 * j] = __nv_bfloat162(l0b, l1b);
    }
}

// ---------------- weight split+transpose: W[K][N] -> hi/lo [N][K] ----------------
__global__ __launch_bounds__(256) void wsplit_t(
    const float* __restrict__ W, __nv_bfloat16* __restrict__ hi,
    __nv_bfloat16* __restrict__ lo, int K, int N)
{
    __shared__ float s[32][33];
    int tx = threadIdx.x & 31, ty = threadIdx.x >> 5;
    int n0 = blockIdx.x * 32, k0 = blockIdx.y * 32;
#pragma unroll
    for (int i = 0; i < 4; i++)
        s[ty + 8 * i][tx] = W[(size_t)(k0 + ty + 8 * i) * N + n0 + tx];
    __syncthreads();
#pragma unroll
    for (int i = 0; i < 4; i++) {
        int n = ty + 8 * i;
        float v = s[tx][n];
        __nv_bfloat16 h = __float2bfloat16_rn(v);
        hi[(size_t)(n0 + n) * K + k0 + tx] = h;
        if (lo) lo[(size_t)(n0 + n) * K + k0 + tx] =
            __float2bfloat16_rn(v - __bfloat162float(h));
    }
}

// ---------------- activation split ----------------
__global__ void split_act(const float* __restrict__ in,
                          __nv_bfloat16* __restrict__ hi,
                          __nv_bfloat16* __restrict__ lo)
{
    int idx = blockIdx.x * 256 + threadIdx.x;
    float4 v = ((const float4*)in)[idx];
    __nv_bfloat16 h0, l0, h1, l1, h2, l2, h3, l3;
    split1(v.x, h0, l0); split1(v.y, h1, l1);
    split1(v.z, h2, l2); split1(v.w, h3, l3);
    ((__nv_bfloat162*)hi)[idx * 2]     = __nv_bfloat162(h0, h1);
    ((__nv_bfloat162*)hi)[idx * 2 + 1] = __nv_bfloat162(h2, h3);
    ((__nv_bfloat162*)lo)[idx * 2]     = __nv_bfloat162(l0, l1);
    ((__nv_bfloat162*)lo)[idx * 2 + 1] = __nv_bfloat162(l2, l3);
}

// ---------------- step-embed add (+split) ----------------
__global__ void add_step_kernel(const float* __restrict__ hidden,
                                const float* __restrict__ se,
                                const int* __restrict__ ts,
                                float* __restrict__ out,
                                __nv_bfloat16* __restrict__ hi,
                                __nv_bfloat16* __restrict__ lo)
{
    int idx = blockIdx.x * 256 + threadIdx.x;
    int c = ts[0];
    if (c > 19) c = 19;
    float4 h = ((const float4*)hidden)[idx];
    float4 s = ((const float4*)(se + c * DMODEL))[idx & 255];
    float4 o = make_float4(h.x + s.x, h.y + s.y, h.z + s.z, h.w + s.w);
    ((float4*)out)[idx] = o;
    __nv_bfloat16 h0, l0, h1, l1, h2, l2, h3, l3;
    split1(o.x, h0, l0); split1(o.y, h1, l1);
    split1(o.z, h2, l2); split1(o.w, h3, l3);
    ((__nv_bfloat162*)hi)[idx * 2]     = __nv_bfloat162(h0, h1);
    ((__nv_bfloat162*)hi)[idx * 2 + 1] = __nv_bfloat162(h2, h3);
    ((__nv_bfloat162*)lo)[idx * 2]     = __nv_bfloat162(l0, l1);
    ((__nv_bfloat162*)lo)[idx * 2 + 1] = __nv_bfloat162(l2, l3);
}

// ---------------- residual + LayerNorm (+ optional split) ----------------
__global__ __launch_bounds__(256) void ln_kernel(
    const float* __restrict__ A, const float* __restrict__ Bx,
    const float* __restrict__ g, const float* __restrict__ beta,
    float* __restrict__ out,
    __nv_bfloat16* __restrict__ hi, __nv_bfloat16* __restrict__ lo)
{
    int row = blockIdx.x, tid = threadIdx.x;
    const float4 va = ((const float4*)(A + (size_t)row * DMODEL))[tid];
    const float4 vb = ((const float4*)(Bx + (size_t)row * DMODEL))[tid];
    float x0 = va.x + vb.x, x1 = va.y + vb.y, x2 = va.z + vb.z, x3 = va.w + vb.w;

    float s = x0 + x1 + x2 + x3;
    float ss = x0 * x0 + x1 * x1 + x2 * x2 + x3 * x3;
#pragma unroll
    for (int o = 16; o > 0; o >>= 1) {
        s  += __shfl_xor_sync(0xffffffffu, s, o);
        ss += __shfl_xor_sync(0xffffffffu, ss, o);
    }
    __shared__ float sb[16];
    int warp = tid >> 5, lane = tid & 31;
    if (lane == 0) { sb[warp] = s; sb[8 + warp] = ss; }
    __syncthreads();
    if (warp == 0) {
        float s2  = (lane < 8) ? sb[lane] : 0.f;
        float ss2 = (lane < 8) ? sb[8 + lane] : 0.f;
#pragma unroll
        for (int o = 4; o > 0; o >>= 1) {
            s2  += __shfl_xor_sync(0xffffffffu, s2, o);
            ss2 += __shfl_xor_sync(0xffffffffu, ss2, o);
        }
        if (lane == 0) { sb[0] = s2; sb[8] = ss2; }
    }
    __syncthreads();
    float mu  = sb[0] * (1.f / 1024.f);
    float var = sb[8] * (1.f / 1024.f) - mu * mu;
    float rstd = rsqrtf(var + 1e-5f);

    float4 go = ((const float4*)g)[tid];
    float4 bo = ((const float4*)beta)[tid];
    float4 r4;
    r4.x = (x0 - mu) * rstd * go.x + bo.x;
    r4.y = (x1 - mu) * rstd * go.y + bo.y;
    r4.z = (x2 - mu) * rstd * go.z + bo.z;
    r4.w = (x3 - mu) * rstd * go.w + bo.w;
    ((float4*)(out + (size_t)row * DMODEL))[tid] = r4;

    if (hi) {
        size_t base = (size_t)row * DMODEL + tid * 4;
        __nv_bfloat16 h0, l0, h1, l1, h2, l2, h3, l3;
        split1(r4.x, h0, l0); split1(r4.y, h1, l1);
        split1(r4.z, h2, l2); split1(r4.w, h3, l3);
        *(__nv_bfloat162*)&hi[base]     = __nv_bfloat162(h0, h1);
        *(__nv_bfloat162*)&hi[base + 2] = __nv_bfloat162(h2, h3);
        *(__nv_bfloat162*)&lo[base]     = __nv_bfloat162(l0, l1);
        *(__nv_bfloat162*)&lo[base + 2] = __nv_bfloat162(l2, l3);
    }
}

// ---------------- orchestration ----------------
extern "C" void kernel_launch(void* const* d_in, const int* in_sizes, int n_in,
                              void* d_out, int out_size)
{
    const float* hidden = (const float*)d_in[0];
    const float* source = (const float*)d_in[1];
    const int*   tstep  = (const int*)d_in[2];
    const float* sembed = (const float*)d_in[3];
    const float* rpb    = (const float*)d_in[4];
    const float* Wqkv = (const float*)d_in[5],  *bqkv = (const float*)d_in[6];
    const float* Wo   = (const float*)d_in[7],  *bo   = (const float*)d_in[8];
    const float* Wcq  = (const float*)d_in[9],  *bcq  = (const float*)d_in[10];
    const float* Wckv = (const float*)d_in[11], *bckv = (const float*)d_in[12];
    const float* Wco  = (const float*)d_in[13], *bco  = (const float*)d_in[14];
    const float* W1   = (const float*)d_in[15], *b1   = (const float*)d_in[16];
    const float* W2   = (const float*)d_in[17], *b2   = (const float*)d_in[18];
    const float* gs = (const float*)d_in[19], *bts = (const float*)d_in[20];
    const float* gc = (const float*)d_in[21], *btc = (const float*)d_in[22];
    const float* gf = (const float*)d_in[23], *btf = (const float*)d_in[24];
    float* out = (float*)d_out;

    float *ph, *pattn, *pproj;
    __nv_bfloat16 *pahi, *palo, *pffhi, *pfflo, *pwhi, *pwlo;
    cudaGetSymbolAddress((void**)&ph,    g_h);
    cudaGetSymbolAddress((void**)&pattn, g_attn);
    cudaGetSymbolAddress((void**)&pproj, g_proj);
    cudaGetSymbolAddress((void**)&pahi,  g_ahi);
    cudaGetSymbolAddress((void**)&palo,  g_alo);
    cudaGetSymbolAddress((void**)&pffhi, g_ffhi);
    cudaGetSymbolAddress((void**)&pfflo, g_fflo);
    cudaGetSymbolAddress((void**)&pwhi,  g_whi);
    cudaGetSymbolAddress((void**)&pwlo,  g_wlo);

    __nv_bfloat16* pqkvb = pffhi;              // qkv bf16 [4096][3072]
    __nv_bfloat16* pcqb  = pfflo;              // cq  bf16 [4096][1024]
    __nv_bfloat16* pckvb = pfflo + 4194304;    // ckv bf16 [4096][2048]

    cudaFuncSetAttribute(gemm_mma<3,0,0>, cudaFuncAttributeMaxDynamicSharedMemorySize, SMEM_GM);
    cudaFuncSetAttribute(gemm_mma<2,1,1>, cudaFuncAttributeMaxDynamicSharedMemorySize, SMEM_GM);
    cudaFuncSetAttribute(gemm_mma<1,0,2>, cudaFuncAttributeMaxDynamicSharedMemorySize, SMEM_GM);
    cudaFuncSetAttribute(attn_tc<0>, cudaFuncAttributeMaxDynamicSharedMemorySize, ATT_SMEM);
    cudaFuncSetAttribute(attn_tc<1>, cudaFuncAttributeMaxDynamicSharedMemorySize, ATT_SMEM);

    // weight split+transpose (lo skipped for 1-pass weights)
    wsplit_t<<<dim3(3072/32, 1024/32), 256>>>(Wqkv, pwhi + OFF_QKV, nullptr,        1024, 3072);
    wsplit_t<<<dim3(1024/32, 1024/32), 256>>>(Wo,   pwhi + OFF_O,   pwlo + OFF_O,   1024, 1024);
    wsplit_t<<<dim3(1024/32, 1024/32), 256>>>(Wcq,  pwhi + OFF_CQ,  nullptr,        1024, 1024);
    wsplit_t<<<dim3(2048/32, 1024/32), 256>>>(Wckv, pwhi + OFF_CKV, nullptr,        1024, 2048);
    wsplit_t<<<dim3(1024/32, 1024/32), 256>>>(Wco,  pwhi + OFF_CO,  pwlo + OFF_CO,  1024, 1024);
    wsplit_t<<<dim3(4096/32, 1024/32), 256>>>(W1,   pwhi + OFF_W1,  pwlo + OFF_W1,  1024, 4096);
    wsplit_t<<<dim3(1024/32, 4096/32), 256>>>(W2,   pwhi + OFF_W2,  pwlo + OFF_W2,  4096, 1024);

    add_step_kernel<<<TOKENS * DMODEL / 1024, 256>>>(hidden, sembed, tstep, ph, pahi, palo);

    // qkv = h0 @ Wqkv -> bf16 (1-pass: output is bf16-rounded anyway)
    gemm_mma<1,0,2><<<dim3(3072/128, TOKENS/128), 256, SMEM_GM>>>(
        pahi, palo, pwhi + OFF_QKV, pwlo + OFF_QKV, bqkv, nullptr, pqkvb, nullptr,
        TOKENS, 3072, 1024);

    dim3 ga(SEQ / 128, NHEAD, 4);
    // self-attn -> bf16 hi/lo directly (Wo input)
    attn_tc<1><<<ga, 256, ATT_SMEM>>>(pqkvb, 3072, pqkvb, 3072, 1024, 2048, rpb, pahi, palo);

    gemm_mma<3,0,0><<<dim3(1024/128, TOKENS/128), 256, SMEM_GM>>>(
        pahi, palo, pwhi + OFF_O, pwlo + OFF_O, bo, pproj, nullptr, nullptr,
        TOKENS, 1024, 1024);
    ln_kernel<<<TOKENS, 256>>>(ph, pproj, gs, bts, ph, pahi, palo);

    gemm_mma<1,0,2><<<dim3(1024/128, TOKENS/128), 256, SMEM_GM>>>(
        pahi, palo, pwhi + OFF_CQ, pwlo + OFF_CQ, bcq, nullptr, pcqb, nullptr,
        TOKENS, 1024, 1024);
    split_act<<<TOKENS * DMODEL / 1024, 256>>>(source, pahi, palo);
    gemm_mma<1,0,2><<<dim3(2048/128, TOKENS/128), 256, SMEM_GM>>>(
        pahi, palo, pwhi + OFF_CKV, pwlo + OFF_CKV, bckv, nullptr, pckvb, nullptr,
        TOKENS, 2048, 1024);

    // cross-attn -> bf16 hi/lo directly (Wco input)
    attn_tc<0><<<ga, 256, ATT_SMEM>>>(pcqb, 1024, pckvb, 2048, 0, 1024, rpb, pahi, palo);

    gemm_mma<3,0,0><<<dim3(1024/128, TOKENS/128), 256, SMEM_GM>>>(
        pahi, palo, pwhi + OFF_CO, pwlo + OFF_CO, bco, pattn, nullptr, nullptr,
        TOKENS, 1024, 1024);
    ln_kernel<<<TOKENS, 256>>>(ph, pattn, gc, btc, ph, pahi, palo);

    gemm_mma<2,1,1><<<dim3(4096/128, TOKENS/128), 256, SMEM_GM>>>(
        pahi, palo, pwhi + OFF_W1, pwlo + OFF_W1, b1, nullptr, pffhi, pfflo,
        TOKENS, 4096, 1024);
    gemm_mma<3,0,0><<<dim3(1024/128, TOKENS/128), 256, SMEM_GM>>>(
        pffhi, pfflo, pwhi + OFF_W2, pwlo + OFF_W2, b2, pproj, nullptr, nullptr,
        TOKENS, 1024, 4096);
    ln_kernel<<<TOKENS, 256>>>(ph, pproj, gf, btf, out, nullptr, nullptr);
}